// round 2
// baseline (speedup 1.0000x reference)
#include <cuda_runtime.h>
#include <cuda_fp16.h>
#include <math.h>

#define NN  100000
#define NE  800000
#define FND 128
#define FED 16
#define HD  200
#define NTW 8
#define DTW 25
#define NG  64
#define NSTEPS 3
#define RT  16     // node rows per block (GEMM tiles)
#define EB  32     // edges per block (edge gate)
#define CC  4      // columns per scatter phase

typedef unsigned long long u64;

// ---------------- scratch (static device memory; no allocation) ----------------
__device__ float     g_h[(size_t)NN * HD];        // row-major h (GEMM/readout)
__device__ float     g_hc[(size_t)HD * NN];       // column-major h (scatter gather)
__device__ float     g_aggc[(size_t)HD * NN];     // column-major agg (scatter target)
__device__ __half    g_eg[(size_t)HD * NE];       // column-major fp16 edge gate
__device__ float     g_score[NN];
__device__ float     g_ex[NN];
__device__ unsigned  g_smax[NG];
__device__ float     g_denom[NG];
__device__ float     g_gfeat[NG * HD];

__device__ __forceinline__ float sigf(float x) { return 1.0f / (1.0f + __expf(-x)); }

// packed f32x2 FMA helpers (FFMA2 — 2 fp32 MACs per instruction)
__device__ __forceinline__ u64 pk2(float lo, float hi) {
    u64 r; asm("mov.b64 %0,{%1,%2};" : "=l"(r) : "f"(lo), "f"(hi)); return r;
}
__device__ __forceinline__ void fma2(u64& d, u64 a, u64 b) {
    asm("fma.rn.f32x2 %0,%1,%2,%0;" : "+l"(d) : "l"(a), "l"(b));
}
__device__ __forceinline__ float red2(u64 v) {
    float a, b; asm("mov.b64 {%0,%1},%2;" : "=f"(a), "=f"(b) : "l"(v)); return a + b;
}

// order-preserving float<->uint encoding for atomicMax on floats
__device__ __forceinline__ unsigned enc_f(float f) {
    unsigned u = __float_as_uint(f);
    return (u & 0x80000000u) ? ~u : (u | 0x80000000u);
}
__device__ __forceinline__ float dec_f(unsigned u) {
    u = (u & 0x80000000u) ? (u & 0x7FFFFFFFu) : ~u;
    return __uint_as_float(u);
}

// ---------------- h0 = relu(X @ W_in + b_in) ----------------
__global__ void k_h0(const float* __restrict__ X, const float* __restrict__ W,
                     const float* __restrict__ b) {
    __shared__ float sX[RT][FND];
    int base = blockIdx.x * RT;
    const float4* src = (const float4*)(X + (size_t)base * FND);
    for (int i = threadIdx.x; i < RT * FND / 4; i += blockDim.x)
        ((float4*)sX)[i] = src[i];
    __syncthreads();
    int j = threadIdx.x;
    if (j >= HD) return;
    u64 acc[RT];
#pragma unroll
    for (int i = 0; i < RT; i++) acc[i] = pk2(b[j], 0.0f);
    for (int k = 0; k < FND; k += 4) {
        u64 w01 = pk2(W[(k + 0) * HD + j], W[(k + 1) * HD + j]);
        u64 w23 = pk2(W[(k + 2) * HD + j], W[(k + 3) * HD + j]);
#pragma unroll
        for (int i = 0; i < RT; i++) {
            float4 x4 = *(const float4*)&sX[i][k];
            fma2(acc[i], pk2(x4.x, x4.y), w01);
            fma2(acc[i], pk2(x4.z, x4.w), w23);
        }
    }
    float tmp[RT];
#pragma unroll
    for (int i = 0; i < RT; i++) {
        float v = fmaxf(red2(acc[i]), 0.0f);
        tmp[i] = v;
        g_h[(size_t)(base + i) * HD + j] = v;
    }
    float4* hc4 = (float4*)(g_hc + (size_t)j * NN + base);
#pragma unroll
    for (int i4 = 0; i4 < RT / 4; i4++)
        hc4[i4] = make_float4(tmp[i4 * 4], tmp[i4 * 4 + 1], tmp[i4 * 4 + 2], tmp[i4 * 4 + 3]);
}

// ------- edge_gate = sigmoid(EF @ W_edge + b_edge), fp16 column-major -------
__global__ void k_eg(const float* __restrict__ EF, const float* __restrict__ W,
                     const float* __restrict__ b) {
    __shared__ float sX[EB][FED];
    int e0 = blockIdx.x * EB;
    const float4* src = (const float4*)(EF + (size_t)e0 * FED);
    for (int i = threadIdx.x; i < EB * FED / 4; i += blockDim.x)
        ((float4*)sX)[i] = src[i];
    __syncthreads();
    int j = threadIdx.x;
    if (j >= HD) return;
    float acc[EB];
#pragma unroll
    for (int i = 0; i < EB; i++) acc[i] = b[j];
#pragma unroll
    for (int k = 0; k < FED; k++) {
        float w = W[k * HD + j];
#pragma unroll
        for (int i = 0; i < EB; i++) acc[i] += sX[i][k] * w;
    }
    __half2* dst = (__half2*)(g_eg + (size_t)j * NE + e0);
#pragma unroll
    for (int i2 = 0; i2 < EB / 2; i2++)
        dst[i2] = __floats2half2_rn(sigf(acc[2 * i2]), sigf(acc[2 * i2 + 1]));
}

// ---------------- zero agg ----------------
__global__ void k_zero_agg() {
    int i = blockIdx.x * blockDim.x + threadIdx.x;
    if (i < NN * HD / 4) ((float4*)g_aggc)[i] = make_float4(0.f, 0.f, 0.f, 0.f);
}

// --------- scatter (column-phased): agg_c[col][dst] += eg[col][e]*h_c[col][src] ---------
__global__ void k_scatter(const int* __restrict__ ei) {
    int e = blockIdx.x * blockDim.x + threadIdx.x;
    if (e >= NE) return;
    int c0 = blockIdx.y * CC;
    int s = ei[e];
    int d = ei[NE + e];
#pragma unroll
    for (int cc = 0; cc < CC; cc++) {
        int col = c0 + cc;
        float eg = __half2float(g_eg[(size_t)col * NE + e]);
        float hv = g_hc[(size_t)col * NN + s];
        atomicAdd(&g_aggc[(size_t)col * NN + d], eg * hv);
    }
}

// ---------------- fused tower + mix + GRU update ----------------
__global__ void k_gru(const float* __restrict__ Wt,
                      const float* __restrict__ Wmix, const float* __restrict__ bmix,
                      const float* __restrict__ Wz, const float* __restrict__ Uz, const float* __restrict__ bz,
                      const float* __restrict__ Wr, const float* __restrict__ Ur, const float* __restrict__ br,
                      const float* __restrict__ Wh, const float* __restrict__ Uh, const float* __restrict__ bh) {
    __shared__ float sA[RT][HD];   // agg -> then m
    __shared__ float sT[RT][HD];   // tower out -> then r*h
    __shared__ float sH[RT][HD];   // h
    int base = blockIdx.x * RT;
    // stage agg from column-major
    for (int j2 = threadIdx.x; j2 < HD; j2 += blockDim.x) {
        const float4* ac4 = (const float4*)(g_aggc + (size_t)j2 * NN + base);
#pragma unroll
        for (int i4 = 0; i4 < RT / 4; i4++) {
            float4 v = ac4[i4];
            sA[i4 * 4 + 0][j2] = v.x;
            sA[i4 * 4 + 1][j2] = v.y;
            sA[i4 * 4 + 2][j2] = v.z;
            sA[i4 * 4 + 3][j2] = v.w;
        }
    }
    // stage h (row-major)
    {
        const float4* h4 = (const float4*)(g_h + (size_t)base * HD);
        for (int i = threadIdx.x; i < RT * HD / 4; i += blockDim.x)
            ((float4*)sH)[i] = h4[i];
    }
    __syncthreads();

    int j = threadIdx.x;
    bool act = (j < HD);
    float zv[RT];

    // ---- tower mixing: sT[n][t*25+e] = sum_d sA[n][t*25+d] * Wt[t][d][e] ----
    if (act) {
        int t = j / DTW, e = j % DTW;
        const float* wt = Wt + (t * DTW) * DTW + e;
        float acc[RT];
#pragma unroll
        for (int i = 0; i < RT; i++) acc[i] = 0.0f;
#pragma unroll
        for (int d = 0; d < DTW; d++) {
            float w = wt[d * DTW];
            int kk = t * DTW + d;
#pragma unroll
            for (int i = 0; i < RT; i++) acc[i] += sA[i][kk] * w;
        }
#pragma unroll
        for (int i = 0; i < RT; i++) sT[i][j] = acc[i];
    }
    __syncthreads();

    // ---- m = relu(sT @ Wmix + bmix) -> sA ----
    if (act) {
        u64 acc[RT];
#pragma unroll
        for (int i = 0; i < RT; i++) acc[i] = pk2(bmix[j], 0.0f);
        for (int k = 0; k < HD; k += 4) {
            u64 w01 = pk2(Wmix[(k + 0) * HD + j], Wmix[(k + 1) * HD + j]);
            u64 w23 = pk2(Wmix[(k + 2) * HD + j], Wmix[(k + 3) * HD + j]);
#pragma unroll
            for (int i = 0; i < RT; i++) {
                float4 a = *(const float4*)&sT[i][k];
                fma2(acc[i], pk2(a.x, a.y), w01);
                fma2(acc[i], pk2(a.z, a.w), w23);
            }
        }
#pragma unroll
        for (int i = 0; i < RT; i++) sA[i][j] = fmaxf(red2(acc[i]), 0.0f);
    }
    __syncthreads();

    // ---- z = sig(m@Wz + h@Uz + bz), r = sig(m@Wr + h@Ur + br); sT = r*h ----
    if (act) {
        u64 accZ[RT], accR[RT];
#pragma unroll
        for (int i = 0; i < RT; i++) { accZ[i] = pk2(bz[j], 0.0f); accR[i] = pk2(br[j], 0.0f); }
        for (int k = 0; k < HD; k += 4) {
            u64 wz01 = pk2(Wz[(k + 0) * HD + j], Wz[(k + 1) * HD + j]);
            u64 wz23 = pk2(Wz[(k + 2) * HD + j], Wz[(k + 3) * HD + j]);
            u64 uz01 = pk2(Uz[(k + 0) * HD + j], Uz[(k + 1) * HD + j]);
            u64 uz23 = pk2(Uz[(k + 2) * HD + j], Uz[(k + 3) * HD + j]);
            u64 wr01 = pk2(Wr[(k + 0) * HD + j], Wr[(k + 1) * HD + j]);
            u64 wr23 = pk2(Wr[(k + 2) * HD + j], Wr[(k + 3) * HD + j]);
            u64 ur01 = pk2(Ur[(k + 0) * HD + j], Ur[(k + 1) * HD + j]);
            u64 ur23 = pk2(Ur[(k + 2) * HD + j], Ur[(k + 3) * HD + j]);
#pragma unroll
            for (int i = 0; i < RT; i++) {
                float4 m4 = *(const float4*)&sA[i][k];
                float4 h4 = *(const float4*)&sH[i][k];
                u64 mA = pk2(m4.x, m4.y), mB = pk2(m4.z, m4.w);
                u64 hA = pk2(h4.x, h4.y), hB = pk2(h4.z, h4.w);
                fma2(accZ[i], mA, wz01); fma2(accZ[i], mB, wz23);
                fma2(accZ[i], hA, uz01); fma2(accZ[i], hB, uz23);
                fma2(accR[i], mA, wr01); fma2(accR[i], mB, wr23);
                fma2(accR[i], hA, ur01); fma2(accR[i], hB, ur23);
            }
        }
#pragma unroll
        for (int i = 0; i < RT; i++) {
            zv[i] = sigf(red2(accZ[i]));
            float r = sigf(red2(accR[i]));
            sT[i][j] = r * sH[i][j];
        }
    }
    __syncthreads();

    // ---- h~ = tanh(m@Wh + (r*h)@Uh + bh); h = (1-z)h + z*h~ ----
    if (act) {
        u64 acc[RT];
#pragma unroll
        for (int i = 0; i < RT; i++) acc[i] = pk2(bh[j], 0.0f);
        for (int k = 0; k < HD; k += 4) {
            u64 w01 = pk2(Wh[(k + 0) * HD + j], Wh[(k + 1) * HD + j]);
            u64 w23 = pk2(Wh[(k + 2) * HD + j], Wh[(k + 3) * HD + j]);
            u64 u01 = pk2(Uh[(k + 0) * HD + j], Uh[(k + 1) * HD + j]);
            u64 u23 = pk2(Uh[(k + 2) * HD + j], Uh[(k + 3) * HD + j]);
#pragma unroll
            for (int i = 0; i < RT; i++) {
                float4 m4 = *(const float4*)&sA[i][k];
                float4 t4 = *(const float4*)&sT[i][k];
                fma2(acc[i], pk2(m4.x, m4.y), w01);
                fma2(acc[i], pk2(m4.z, m4.w), w23);
                fma2(acc[i], pk2(t4.x, t4.y), u01);
                fma2(acc[i], pk2(t4.z, t4.w), u23);
            }
        }
        float tmp[RT];
#pragma unroll
        for (int i = 0; i < RT; i++) {
            float ht = tanhf(red2(acc[i]));
            float hn = (1.0f - zv[i]) * sH[i][j] + zv[i] * ht;
            tmp[i] = hn;
            g_h[(size_t)(base + i) * HD + j] = hn;
        }
        float4* hc4 = (float4*)(g_hc + (size_t)j * NN + base);
#pragma unroll
        for (int i4 = 0; i4 < RT / 4; i4++)
            hc4[i4] = make_float4(tmp[i4 * 4], tmp[i4 * 4 + 1], tmp[i4 * 4 + 2], tmp[i4 * 4 + 3]);
    }
}

// ---------------- init readout scratch ----------------
__global__ void k_init_small() {
    int t = blockIdx.x * blockDim.x + threadIdx.x;
    for (int i = t; i < NG * HD; i += gridDim.x * blockDim.x) g_gfeat[i] = 0.0f;
    if (t < NG) { g_denom[t] = 0.0f; g_smax[t] = enc_f(-INFINITY); }
}

// ---------------- score + segment max ----------------
__global__ void k_score(const float* __restrict__ Ws, const float* __restrict__ bs,
                        const int* __restrict__ bv) {
    int n = blockIdx.x * 8 + (threadIdx.x >> 5);
    if (n >= NN) return;
    int lane = threadIdx.x & 31;
    float acc = 0.0f;
    for (int k = lane; k < HD; k += 32) acc += g_h[(size_t)n * HD + k] * Ws[k];
#pragma unroll
    for (int o = 16; o; o >>= 1) acc += __shfl_xor_sync(0xffffffffu, acc, o);
    if (lane == 0) {
        float s = acc + bs[0];
        g_score[n] = s;
        atomicMax(&g_smax[bv[n]], enc_f(s));
    }
}

// ---------------- exp + segment sum (run-length aggregated) ----------------
__global__ void k_exp(const int* __restrict__ bv) {
    int n0 = (blockIdx.x * blockDim.x + threadIdx.x) * 16;
    if (n0 >= NN) return;
    int end = n0 + 16; if (end > NN) end = NN;
    int cb = bv[n0];
    float mx = dec_f(g_smax[cb]);
    float run = 0.0f;
    for (int n = n0; n < end; n++) {
        int b = bv[n];
        if (b != cb) {
            atomicAdd(&g_denom[cb], run);
            run = 0.0f; cb = b; mx = dec_f(g_smax[b]);
        }
        float ex = __expf(g_score[n] - mx);
        g_ex[n] = ex;
        run += ex;
    }
    atomicAdd(&g_denom[cb], run);
}

// ---------------- feat = h@W_feat + b_feat; g[b] += alpha * feat ----------------
__global__ void k_feat(const float* __restrict__ Wf, const float* __restrict__ bf,
                       const int* __restrict__ bv) {
    __shared__ float sHt[RT][HD];
    __shared__ float sAl[RT];
    __shared__ int   sB[RT];
    int base = blockIdx.x * RT;
    {
        const float4* h4 = (const float4*)(g_h + (size_t)base * HD);
        for (int i = threadIdx.x; i < RT * HD / 4; i += blockDim.x)
            ((float4*)sHt)[i] = h4[i];
    }
    if (threadIdx.x < RT) {
        int n = base + threadIdx.x;
        int b = bv[n];
        sB[threadIdx.x] = b;
        sAl[threadIdx.x] = g_ex[n] / g_denom[b];
    }
    __syncthreads();
    int j = threadIdx.x;
    if (j >= HD) return;
    u64 acc2[RT];
#pragma unroll
    for (int i = 0; i < RT; i++) acc2[i] = pk2(bf[j], 0.0f);
    for (int k = 0; k < HD; k += 4) {
        u64 w01 = pk2(Wf[(k + 0) * HD + j], Wf[(k + 1) * HD + j]);
        u64 w23 = pk2(Wf[(k + 2) * HD + j], Wf[(k + 3) * HD + j]);
#pragma unroll
        for (int i = 0; i < RT; i++) {
            float4 h4 = *(const float4*)&sHt[i][k];
            fma2(acc2[i], pk2(h4.x, h4.y), w01);
            fma2(acc2[i], pk2(h4.z, h4.w), w23);
        }
    }
    // run-length aggregate atomics (batch_vector is sorted)
    float run = 0.0f;
    int cb = sB[0];
#pragma unroll
    for (int i = 0; i < RT; i++) {
        if (sB[i] != cb) {
            atomicAdd(&g_gfeat[cb * HD + j], run);
            run = 0.0f; cb = sB[i];
        }
        run += sAl[i] * red2(acc2[i]);
    }
    atomicAdd(&g_gfeat[cb * HD + j], run);
}

// ---------------- readout MLP: out = relu(g@W_r1+b_r1)@W_out + b_out ----------------
__global__ void k_readout(const float* __restrict__ Wr1, const float* __restrict__ br1,
                          const float* __restrict__ Wout, const float* __restrict__ bout,
                          float* __restrict__ out) {
    __shared__ float sG[HD];
    __shared__ float sRed[256];
    int g = blockIdx.x;
    for (int k = threadIdx.x; k < HD; k += blockDim.x) sG[k] = g_gfeat[g * HD + k];
    __syncthreads();
    float p = 0.0f;
    int j = threadIdx.x;
    if (j < HD) {
        float acc = br1[j];
        for (int k = 0; k < HD; k++) acc += sG[k] * Wr1[k * HD + j];
        p = fmaxf(acc, 0.0f) * Wout[j];
    }
    sRed[threadIdx.x] = p;
    __syncthreads();
    for (int s = 128; s; s >>= 1) {
        if (threadIdx.x < s) sRed[threadIdx.x] += sRed[threadIdx.x + s];
        __syncthreads();
    }
    if (threadIdx.x == 0) out[g] = sRed[0] + bout[0];
}

// ---------------- launch ----------------
extern "C" void kernel_launch(void* const* d_in, const int* in_sizes, int n_in,
                              void* d_out, int out_size) {
    const float* node_features = (const float*)d_in[0];
    const float* edge_features = (const float*)d_in[1];
    const int*   edge_index    = (const int*)d_in[2];
    const int*   batch_vector  = (const int*)d_in[3];
    const float* W_in   = (const float*)d_in[4];
    const float* b_in   = (const float*)d_in[5];
    const float* W_edge = (const float*)d_in[6];
    const float* b_edge = (const float*)d_in[7];
    const float* W_tower= (const float*)d_in[8];
    const float* W_mix  = (const float*)d_in[9];
    const float* b_mix  = (const float*)d_in[10];
    const float* Wz = (const float*)d_in[11];
    const float* Uz = (const float*)d_in[12];
    const float* bz = (const float*)d_in[13];
    const float* Wr = (const float*)d_in[14];
    const float* Ur = (const float*)d_in[15];
    const float* br = (const float*)d_in[16];
    const float* Wh = (const float*)d_in[17];
    const float* Uh = (const float*)d_in[18];
    const float* bh = (const float*)d_in[19];
    const float* W_score = (const float*)d_in[20];
    const float* b_score = (const float*)d_in[21];
    const float* W_feat  = (const float*)d_in[22];
    const float* b_feat  = (const float*)d_in[23];
    const float* W_r1    = (const float*)d_in[24];
    const float* b_r1    = (const float*)d_in[25];
    const float* W_out   = (const float*)d_in[26];
    const float* b_out   = (const float*)d_in[27];
    float* out = (float*)d_out;

    k_h0<<<NN / RT, 224>>>(node_features, W_in, b_in);
    k_eg<<<NE / EB, 224>>>(edge_features, W_edge, b_edge);

    for (int s = 0; s < NSTEPS; s++) {
        k_zero_agg<<<(NN * HD / 4 + 255) / 256, 256>>>();
        dim3 sg((NE + 255) / 256, HD / CC);
        k_scatter<<<sg, 256>>>(edge_index);
        k_gru<<<NN / RT, 224>>>(W_tower, W_mix, b_mix,
                                Wz, Uz, bz, Wr, Ur, br, Wh, Uh, bh);
    }

    k_init_small<<<50, 256>>>();
    k_score<<<(NN + 7) / 8, 256>>>(W_score, b_score, batch_vector);
    k_exp<<<(NN / 16 + 255) / 256, 256>>>(batch_vector);
    k_feat<<<NN / RT, 224>>>(W_feat, b_feat, batch_vector);
    k_readout<<<NG, 256>>>(W_r1, b_r1, W_out, b_out, out);
}

// round 3
// speedup vs baseline: 1.0921x; 1.0921x over previous
#include <cuda_runtime.h>
#include <math.h>

#define NN  100000
#define NE  800000
#define FND 128
#define FED 16
#define HD  200
#define NTW 8
#define DTW 25
#define NG  64
#define NSTEPS 3
#define RT  16     // node rows per block (GEMM tiles)
#define RE  32     // edge rows per block (edge gate)

typedef unsigned long long u64;

// ---------------- scratch (static device memory; no allocation) ----------------
__device__ float     g_h[(size_t)NN * HD];       // 80 MB
__device__ float     g_agg[(size_t)NN * HD];     // 80 MB
__device__ float     g_eg[(size_t)NE * HD];      // 640 MB
__device__ float     g_score[NN];
__device__ float     g_ex[NN];
__device__ unsigned  g_smax[NG];
__device__ float     g_denom[NG];
__device__ float     g_gfeat[NG * HD];
// transposed weights: row j holds contiguous k (for LDG.128 of packed pairs)
__device__ float     g_Wmix_t[HD * HD];
__device__ float     g_Wz_t[HD * HD];
__device__ float     g_Uz_t[HD * HD];
__device__ float     g_Wr_t[HD * HD];
__device__ float     g_Ur_t[HD * HD];
__device__ float     g_Wh_t[HD * HD];
__device__ float     g_Uh_t[HD * HD];
__device__ float     g_Wf_t[HD * HD];
__device__ float     g_Win_t[HD * FND];

__device__ __forceinline__ float sigf(float x) { return 1.0f / (1.0f + __expf(-x)); }

// packed f32x2 FMA: d(pair) += a(pair) * b(pair). One instr = 2 fp32 MACs.
__device__ __forceinline__ void fma2(u64& d, u64 a, u64 b) {
    asm("fma.rn.f32x2 %0,%1,%2,%0;" : "+l"(d) : "l"(a), "l"(b));
}
__device__ __forceinline__ float red2(u64 v) {
    float a, b; asm("mov.b64 {%0,%1},%2;" : "=f"(a), "=f"(b) : "l"(v)); return a + b;
}
__device__ __forceinline__ u64 pk2(float lo, float hi) {
    u64 r; asm("mov.b64 %0,{%1,%2};" : "=l"(r) : "f"(lo), "f"(hi)); return r;
}

// order-preserving float<->uint encoding for atomicMax on floats
__device__ __forceinline__ unsigned enc_f(float f) {
    unsigned u = __float_as_uint(f);
    return (u & 0x80000000u) ? ~u : (u | 0x80000000u);
}
__device__ __forceinline__ float dec_f(unsigned u) {
    u = (u & 0x80000000u) ? (u & 0x7FFFFFFFu) : ~u;
    return __uint_as_float(u);
}

// ---------------- generic transpose: dst[j*K+k] = src[k*J+j]  (src is [K][J]) ----
__global__ void k_tr(const float* __restrict__ src, float* __restrict__ dst,
                     int K, int J) {
    int idx = blockIdx.x * blockDim.x + threadIdx.x;
    if (idx >= K * J) return;
    int j = idx / K, k = idx - j * K;
    dst[j * K + k] = src[k * J + j];
}

// ---------------- h0 = relu(X @ W_in + b_in)  [FFMA2] ----------------
__global__ void k_h0(const float* __restrict__ X, const float* __restrict__ b) {
    __shared__ __align__(16) float sX[RT][FND];
    int base = blockIdx.x * RT;
    const float4* src = (const float4*)(X + (size_t)base * FND);
    for (int i = threadIdx.x; i < RT * FND / 4; i += blockDim.x)
        ((float4*)sX)[i] = src[i];
    __syncthreads();
    int j = threadIdx.x;
    if (j >= HD) return;
    u64 acc[RT];
#pragma unroll
    for (int i = 0; i < RT; i++) acc[i] = pk2(b[j], 0.0f);
    const float* wrow = g_Win_t + j * FND;
    for (int k = 0; k < FND; k += 4) {
        ulonglong2 w = *(const ulonglong2*)(wrow + k);
#pragma unroll
        for (int i = 0; i < RT; i++) {
            ulonglong2 x = *(const ulonglong2*)&sX[i][k];
            fma2(acc[i], x.x, w.x);
            fma2(acc[i], x.y, w.y);
        }
    }
#pragma unroll
    for (int i = 0; i < RT; i++)
        g_h[(size_t)(base + i) * HD + j] = fmaxf(red2(acc[i]), 0.0f);
}

// ---------------- edge_gate = sigmoid(EF @ W_edge + b_edge) ----------------
__global__ void k_eg(const float* __restrict__ EF, const float* __restrict__ W,
                     const float* __restrict__ b) {
    __shared__ __align__(16) float sX[RE][FED];
    int base = blockIdx.x * RE;
    const float4* src = (const float4*)(EF + (size_t)base * FED);
    for (int i = threadIdx.x; i < RE * FED / 4; i += blockDim.x)
        ((float4*)sX)[i] = src[i];
    __syncthreads();
    int j = threadIdx.x;
    if (j >= HD) return;
    float acc[RE];
#pragma unroll
    for (int i = 0; i < RE; i++) acc[i] = b[j];
#pragma unroll
    for (int k = 0; k < FED; k++) {
        float w = W[k * HD + j];
#pragma unroll
        for (int i = 0; i < RE; i++) acc[i] += sX[i][k] * w;
    }
#pragma unroll
    for (int i = 0; i < RE; i++)
        g_eg[(size_t)(base + i) * HD + j] = sigf(acc[i]);
}

// ---------------- zero agg ----------------
__global__ void k_zero_agg() {
    int i = blockIdx.x * blockDim.x + threadIdx.x;
    if (i < NN * HD / 4) ((float4*)g_agg)[i] = make_float4(0.f, 0.f, 0.f, 0.f);
}

// ---------------- scatter: agg[dst] += eg[e] * h[src] ----------------
__global__ void k_scatter(const int* __restrict__ ei) {
    int idx = blockIdx.x * blockDim.x + threadIdx.x;
    if (idx >= NE * (HD / 4)) return;
    int e = idx / (HD / 4);
    int c = (idx - e * (HD / 4)) * 4;
    int s = ei[e];
    int d = ei[NE + e];
    float4 eg = *(const float4*)&g_eg[(size_t)e * HD + c];
    float4 hv = *(const float4*)&g_h[(size_t)s * HD + c];
    float* p = &g_agg[(size_t)d * HD + c];
    atomicAdd(p + 0, eg.x * hv.x);
    atomicAdd(p + 1, eg.y * hv.y);
    atomicAdd(p + 2, eg.z * hv.z);
    atomicAdd(p + 3, eg.w * hv.w);
}

// ---------------- fused tower + mix + GRU update  [FFMA2, split passes] ----------------
__global__ void k_gru(const float* __restrict__ Wt,
                      const float* __restrict__ bmix,
                      const float* __restrict__ bz,
                      const float* __restrict__ br,
                      const float* __restrict__ bh) {
    __shared__ __align__(16) float sA[RT][HD];   // agg -> then m
    __shared__ __align__(16) float sT[RT][HD];   // tower out -> then r*h
    __shared__ __align__(16) float sH[RT][HD];   // h
    int base = blockIdx.x * RT;
    {
        const float4* a4 = (const float4*)(g_agg + (size_t)base * HD);
        const float4* h4 = (const float4*)(g_h + (size_t)base * HD);
        for (int i = threadIdx.x; i < RT * HD / 4; i += blockDim.x) {
            ((float4*)sA)[i] = a4[i];
            ((float4*)sH)[i] = h4[i];
        }
    }
    __syncthreads();

    int j = threadIdx.x;
    bool act = (j < HD);
    float zv[RT];

    // ---- tower mixing: sT[n][t*25+e] = sum_d sA[n][t*25+d] * Wt[t][d][e] ----
    if (act) {
        int t = j / DTW, e = j % DTW;
        const float* wt = Wt + (t * DTW) * DTW + e;
        float acc[RT];
#pragma unroll
        for (int i = 0; i < RT; i++) acc[i] = 0.0f;
#pragma unroll
        for (int d = 0; d < DTW; d++) {
            float w = wt[d * DTW];
            int kk = t * DTW + d;
#pragma unroll
            for (int i = 0; i < RT; i++) acc[i] += sA[i][kk] * w;
        }
#pragma unroll
        for (int i = 0; i < RT; i++) sT[i][j] = acc[i];
    }
    __syncthreads();

    // ---- m = relu(sT @ Wmix + bmix) -> sA ----
    if (act) {
        u64 acc[RT];
#pragma unroll
        for (int i = 0; i < RT; i++) acc[i] = pk2(bmix[j], 0.0f);
        const float* wrow = g_Wmix_t + j * HD;
        for (int k = 0; k < HD; k += 4) {
            ulonglong2 w = *(const ulonglong2*)(wrow + k);
#pragma unroll
            for (int i = 0; i < RT; i++) {
                ulonglong2 a = *(const ulonglong2*)&sT[i][k];
                fma2(acc[i], a.x, w.x);
                fma2(acc[i], a.y, w.y);
            }
        }
#pragma unroll
        for (int i = 0; i < RT; i++) sA[i][j] = fmaxf(red2(acc[i]), 0.0f);
    }
    __syncthreads();

    // ---- Z pass: z = sig(m@Wz + h@Uz + bz) ----
    if (act) {
        u64 acc[RT];
#pragma unroll
        for (int i = 0; i < RT; i++) acc[i] = pk2(bz[j], 0.0f);
        const float* wrow = g_Wz_t + j * HD;
        const float* urow = g_Uz_t + j * HD;
        for (int k = 0; k < HD; k += 4) {
            ulonglong2 w = *(const ulonglong2*)(wrow + k);
            ulonglong2 u = *(const ulonglong2*)(urow + k);
#pragma unroll
            for (int i = 0; i < RT; i++) {
                ulonglong2 m = *(const ulonglong2*)&sA[i][k];
                ulonglong2 h = *(const ulonglong2*)&sH[i][k];
                fma2(acc[i], m.x, w.x);
                fma2(acc[i], m.y, w.y);
                fma2(acc[i], h.x, u.x);
                fma2(acc[i], h.y, u.y);
            }
        }
#pragma unroll
        for (int i = 0; i < RT; i++) zv[i] = sigf(red2(acc[i]));
    }

    // ---- R pass: r = sig(m@Wr + h@Ur + br); sT = r*h ----
    if (act) {
        u64 acc[RT];
#pragma unroll
        for (int i = 0; i < RT; i++) acc[i] = pk2(br[j], 0.0f);
        const float* wrow = g_Wr_t + j * HD;
        const float* urow = g_Ur_t + j * HD;
        for (int k = 0; k < HD; k += 4) {
            ulonglong2 w = *(const ulonglong2*)(wrow + k);
            ulonglong2 u = *(const ulonglong2*)(urow + k);
#pragma unroll
            for (int i = 0; i < RT; i++) {
                ulonglong2 m = *(const ulonglong2*)&sA[i][k];
                ulonglong2 h = *(const ulonglong2*)&sH[i][k];
                fma2(acc[i], m.x, w.x);
                fma2(acc[i], m.y, w.y);
                fma2(acc[i], h.x, u.x);
                fma2(acc[i], h.y, u.y);
            }
        }
#pragma unroll
        for (int i = 0; i < RT; i++) {
            float r = sigf(red2(acc[i]));
            sT[i][j] = r * sH[i][j];
        }
    }
    __syncthreads();

    // ---- H pass: h~ = tanh(m@Wh + (r*h)@Uh + bh); h = (1-z)h + z*h~ ----
    if (act) {
        u64 acc[RT];
#pragma unroll
        for (int i = 0; i < RT; i++) acc[i] = pk2(bh[j], 0.0f);
        const float* wrow = g_Wh_t + j * HD;
        const float* urow = g_Uh_t + j * HD;
        for (int k = 0; k < HD; k += 4) {
            ulonglong2 w = *(const ulonglong2*)(wrow + k);
            ulonglong2 u = *(const ulonglong2*)(urow + k);
#pragma unroll
            for (int i = 0; i < RT; i++) {
                ulonglong2 m = *(const ulonglong2*)&sA[i][k];
                ulonglong2 t = *(const ulonglong2*)&sT[i][k];
                fma2(acc[i], m.x, w.x);
                fma2(acc[i], m.y, w.y);
                fma2(acc[i], t.x, u.x);
                fma2(acc[i], t.y, u.y);
            }
        }
#pragma unroll
        for (int i = 0; i < RT; i++) {
            float ht = tanhf(red2(acc[i]));
            g_h[(size_t)(base + i) * HD + j] = (1.0f - zv[i]) * sH[i][j] + zv[i] * ht;
        }
    }
}

// ---------------- init readout scratch ----------------
__global__ void k_init_small() {
    int t = blockIdx.x * blockDim.x + threadIdx.x;
    for (int i = t; i < NG * HD; i += gridDim.x * blockDim.x) g_gfeat[i] = 0.0f;
    if (t < NG) { g_denom[t] = 0.0f; g_smax[t] = enc_f(-INFINITY); }
}

// ---------------- score + segment max ----------------
__global__ void k_score(const float* __restrict__ Ws, const float* __restrict__ bs,
                        const int* __restrict__ bv) {
    int n = blockIdx.x * 8 + (threadIdx.x >> 5);
    if (n >= NN) return;
    int lane = threadIdx.x & 31;
    float acc = 0.0f;
    for (int k = lane; k < HD; k += 32) acc += g_h[(size_t)n * HD + k] * Ws[k];
#pragma unroll
    for (int o = 16; o; o >>= 1) acc += __shfl_xor_sync(0xffffffffu, acc, o);
    if (lane == 0) {
        float s = acc + bs[0];
        g_score[n] = s;
        atomicMax(&g_smax[bv[n]], enc_f(s));
    }
}

// ---------------- exp + segment sum (run-length aggregated) ----------------
__global__ void k_exp(const int* __restrict__ bv) {
    int n0 = (blockIdx.x * blockDim.x + threadIdx.x) * 16;
    if (n0 >= NN) return;
    int end = n0 + 16; if (end > NN) end = NN;
    int cb = bv[n0];
    float mx = dec_f(g_smax[cb]);
    float run = 0.0f;
    for (int n = n0; n < end; n++) {
        int b = bv[n];
        if (b != cb) {
            atomicAdd(&g_denom[cb], run);
            run = 0.0f; cb = b; mx = dec_f(g_smax[b]);
        }
        float ex = __expf(g_score[n] - mx);
        g_ex[n] = ex;
        run += ex;
    }
    atomicAdd(&g_denom[cb], run);
}

// ---------------- feat = h@W_feat + b_feat; g[b] += alpha * feat  [FFMA2] -------
__global__ void k_feat(const float* __restrict__ bf, const int* __restrict__ bv) {
    __shared__ __align__(16) float sHt[RT][HD];
    __shared__ float sAl[RT];
    __shared__ int   sB[RT];
    int base = blockIdx.x * RT;
    {
        const float4* h4 = (const float4*)(g_h + (size_t)base * HD);
        for (int i = threadIdx.x; i < RT * HD / 4; i += blockDim.x)
            ((float4*)sHt)[i] = h4[i];
    }
    if (threadIdx.x < RT) {
        int n = base + threadIdx.x;
        int b = bv[n];
        sB[threadIdx.x] = b;
        sAl[threadIdx.x] = g_ex[n] / g_denom[b];
    }
    __syncthreads();
    int j = threadIdx.x;
    if (j >= HD) return;
    u64 acc[RT];
#pragma unroll
    for (int i = 0; i < RT; i++) acc[i] = pk2(bf[j], 0.0f);
    const float* wrow = g_Wf_t + j * HD;
    for (int k = 0; k < HD; k += 4) {
        ulonglong2 w = *(const ulonglong2*)(wrow + k);
#pragma unroll
        for (int i = 0; i < RT; i++) {
            ulonglong2 h = *(const ulonglong2*)&sHt[i][k];
            fma2(acc[i], h.x, w.x);
            fma2(acc[i], h.y, w.y);
        }
    }
    // run-length aggregate atomics (batch_vector is sorted)
    float run = 0.0f;
    int cb = sB[0];
#pragma unroll
    for (int i = 0; i < RT; i++) {
        if (sB[i] != cb) {
            atomicAdd(&g_gfeat[cb * HD + j], run);
            run = 0.0f; cb = sB[i];
        }
        run += sAl[i] * red2(acc[i]);
    }
    atomicAdd(&g_gfeat[cb * HD + j], run);
}

// ---------------- readout MLP: out = relu(g@W_r1+b_r1)@W_out + b_out ----------------
__global__ void k_readout(const float* __restrict__ Wr1, const float* __restrict__ br1,
                          const float* __restrict__ Wout, const float* __restrict__ bout,
                          float* __restrict__ out) {
    __shared__ float sG[HD];
    __shared__ float sRed[256];
    int g = blockIdx.x;
    for (int k = threadIdx.x; k < HD; k += blockDim.x) sG[k] = g_gfeat[g * HD + k];
    __syncthreads();
    float p = 0.0f;
    int j = threadIdx.x;
    if (j < HD) {
        float acc = br1[j];
        for (int k = 0; k < HD; k++) acc += sG[k] * Wr1[k * HD + j];
        p = fmaxf(acc, 0.0f) * Wout[j];
    }
    sRed[threadIdx.x] = p;
    __syncthreads();
    for (int s = 128; s; s >>= 1) {
        if (threadIdx.x < s) sRed[threadIdx.x] += sRed[threadIdx.x + s];
        __syncthreads();
    }
    if (threadIdx.x == 0) out[g] = sRed[0] + bout[0];
}

// helper for transposed weight pointers (device symbols addressable from host code
// only via kernels; we pass them through kernel params by taking device addresses
// inside a tiny kernel is not allowed — instead use separate launches with symbol refs)
__global__ void k_tr_to(const float* __restrict__ src, int K, int J, int which) {
    float* dst;
    switch (which) {
        case 0: dst = g_Wmix_t; break;
        case 1: dst = g_Wz_t; break;
        case 2: dst = g_Uz_t; break;
        case 3: dst = g_Wr_t; break;
        case 4: dst = g_Ur_t; break;
        case 5: dst = g_Wh_t; break;
        case 6: dst = g_Uh_t; break;
        case 7: dst = g_Wf_t; break;
        default: dst = g_Win_t; break;
    }
    int idx = blockIdx.x * blockDim.x + threadIdx.x;
    if (idx >= K * J) return;
    int j = idx / K, k = idx - j * K;
    dst[j * K + k] = src[k * J + j];
}

// ---------------- launch ----------------
extern "C" void kernel_launch(void* const* d_in, const int* in_sizes, int n_in,
                              void* d_out, int out_size) {
    const float* node_features = (const float*)d_in[0];
    const float* edge_features = (const float*)d_in[1];
    const int*   edge_index    = (const int*)d_in[2];
    const int*   batch_vector  = (const int*)d_in[3];
    const float* W_in   = (const float*)d_in[4];
    const float* b_in   = (const float*)d_in[5];
    const float* W_edge = (const float*)d_in[6];
    const float* b_edge = (const float*)d_in[7];
    const float* W_tower= (const float*)d_in[8];
    const float* W_mix  = (const float*)d_in[9];
    const float* b_mix  = (const float*)d_in[10];
    const float* Wz = (const float*)d_in[11];
    const float* Uz = (const float*)d_in[12];
    const float* bz = (const float*)d_in[13];
    const float* Wr = (const float*)d_in[14];
    const float* Ur = (const float*)d_in[15];
    const float* br = (const float*)d_in[16];
    const float* Wh = (const float*)d_in[17];
    const float* Uh = (const float*)d_in[18];
    const float* bh = (const float*)d_in[19];
    const float* W_score = (const float*)d_in[20];
    const float* b_score = (const float*)d_in[21];
    const float* W_feat  = (const float*)d_in[22];
    const float* b_feat  = (const float*)d_in[23];
    const float* W_r1    = (const float*)d_in[24];
    const float* b_r1    = (const float*)d_in[25];
    const float* W_out   = (const float*)d_in[26];
    const float* b_out   = (const float*)d_in[27];
    float* out = (float*)d_out;

    // one-time (per launch) weight transposes
    int nb = (HD * HD + 255) / 256;
    k_tr_to<<<nb, 256>>>(W_mix, HD, HD, 0);
    k_tr_to<<<nb, 256>>>(Wz,    HD, HD, 1);
    k_tr_to<<<nb, 256>>>(Uz,    HD, HD, 2);
    k_tr_to<<<nb, 256>>>(Wr,    HD, HD, 3);
    k_tr_to<<<nb, 256>>>(Ur,    HD, HD, 4);
    k_tr_to<<<nb, 256>>>(Wh,    HD, HD, 5);
    k_tr_to<<<nb, 256>>>(Uh,    HD, HD, 6);
    k_tr_to<<<nb, 256>>>(W_feat,HD, HD, 7);
    k_tr_to<<<(FND * HD + 255) / 256, 256>>>(W_in, FND, HD, 8);

    k_h0<<<NN / RT, 224>>>(node_features, b_in);
    k_eg<<<NE / RE, 224>>>(edge_features, W_edge, b_edge);

    for (int s = 0; s < NSTEPS; s++) {
        k_zero_agg<<<(NN * HD / 4 + 255) / 256, 256>>>();
        k_scatter<<<(NE * (HD / 4) + 255) / 256, 256>>>(edge_index);
        k_gru<<<NN / RT, 224>>>(W_tower, b_mix, bz, br, bh);
    }

    k_init_small<<<50, 256>>>();
    k_score<<<(NN + 7) / 8, 256>>>(W_score, b_score, batch_vector);
    k_exp<<<(NN / 16 + 255) / 256, 256>>>(batch_vector);
    k_feat<<<NN / RT, 224>>>(b_feat, batch_vector);
    k_readout<<<NG, 256>>>(W_r1, b_r1, W_out, b_out, out);
}

// round 4
// speedup vs baseline: 1.2162x; 1.1136x over previous
#include <cuda_runtime.h>
#include <math.h>

#define NN  100000
#define NE  800000
#define FND 128
#define FED 16
#define HD  200
#define NTW 8
#define DTW 25
#define NG  64
#define NSTEPS 3
#define RT  16     // node rows per block (GEMM tiles)
#define RE  32     // edge rows per block (edge gate)

typedef unsigned long long u64;

// ---------------- scratch (static device memory; no allocation) ----------------
__device__ float     g_h[(size_t)NN * HD];       // 80 MB
__device__ float     g_agg[(size_t)NN * HD];     // 80 MB
__device__ float     g_eg[(size_t)NE * HD];      // 640 MB
__device__ float     g_score[NN];
__device__ float     g_ex[NN];
__device__ unsigned  g_smax[NG];
__device__ float     g_denom[NG];
__device__ float     g_gfeat[NG * HD];
// pair-interleaved weights: Wp[k/2][j] = (W[k][j], W[k+1][j]) stored as u64.
// Thread j loads Wp[p*HD + j]: coalesced LDG.64, value is a ready f32x2 pair.
__device__ u64       g_Wmix_p[(HD / 2) * HD];
__device__ u64       g_Wz_p[(HD / 2) * HD];
__device__ u64       g_Uz_p[(HD / 2) * HD];
__device__ u64       g_Wr_p[(HD / 2) * HD];
__device__ u64       g_Ur_p[(HD / 2) * HD];
__device__ u64       g_Wh_p[(HD / 2) * HD];
__device__ u64       g_Uh_p[(HD / 2) * HD];
__device__ u64       g_Wf_p[(HD / 2) * HD];
__device__ u64       g_Win_p[(FND / 2) * HD];

__device__ __forceinline__ float sigf(float x) { return 1.0f / (1.0f + __expf(-x)); }

// packed f32x2 FMA: d(pair) += a(pair) * b(pair). One instr = 2 fp32 MACs.
__device__ __forceinline__ void fma2(u64& d, u64 a, u64 b) {
    asm("fma.rn.f32x2 %0,%1,%2,%0;" : "+l"(d) : "l"(a), "l"(b));
}
__device__ __forceinline__ float red2(u64 v) {
    float a, b; asm("mov.b64 {%0,%1},%2;" : "=f"(a), "=f"(b) : "l"(v)); return a + b;
}
__device__ __forceinline__ u64 pk2(float lo, float hi) {
    u64 r; asm("mov.b64 %0,{%1,%2};" : "=l"(r) : "f"(lo), "f"(hi)); return r;
}

// order-preserving float<->uint encoding for atomicMax on floats
__device__ __forceinline__ unsigned enc_f(float f) {
    unsigned u = __float_as_uint(f);
    return (u & 0x80000000u) ? ~u : (u | 0x80000000u);
}
__device__ __forceinline__ float dec_f(unsigned u) {
    u = (u & 0x80000000u) ? (u & 0x7FFFFFFFu) : ~u;
    return __uint_as_float(u);
}

// ------- pack: dst[p*J + j] = (src[2p*J + j], src[(2p+1)*J + j])  [coalesced r/w] -------
__global__ void k_pack(const float* __restrict__ src, int K, int J, int which) {
    u64* dst;
    switch (which) {
        case 0: dst = g_Wmix_p; break;
        case 1: dst = g_Wz_p; break;
        case 2: dst = g_Uz_p; break;
        case 3: dst = g_Wr_p; break;
        case 4: dst = g_Ur_p; break;
        case 5: dst = g_Wh_p; break;
        case 6: dst = g_Uh_p; break;
        case 7: dst = g_Wf_p; break;
        default: dst = g_Win_p; break;
    }
    int idx = blockIdx.x * blockDim.x + threadIdx.x;   // idx = p*J + j
    if (idx >= (K / 2) * J) return;
    int p = idx / J, j = idx - p * J;
    dst[idx] = pk2(src[(2 * p) * J + j], src[(2 * p + 1) * J + j]);
}

// ---------------- h0 = relu(X @ W_in + b_in)  [FFMA2, paired weights] ----------------
__global__ void k_h0(const float* __restrict__ X, const float* __restrict__ b) {
    __shared__ __align__(16) float sX[RT][FND];
    int base = blockIdx.x * RT;
    const float4* src = (const float4*)(X + (size_t)base * FND);
    for (int i = threadIdx.x; i < RT * FND / 4; i += blockDim.x)
        ((float4*)sX)[i] = src[i];
    __syncthreads();
    int j = threadIdx.x;
    if (j >= HD) return;
    u64 acc[RT];
#pragma unroll
    for (int i = 0; i < RT; i++) acc[i] = pk2(b[j], 0.0f);
    for (int k = 0; k < FND; k += 4) {
        u64 w01 = g_Win_p[(k / 2) * HD + j];
        u64 w23 = g_Win_p[(k / 2 + 1) * HD + j];
#pragma unroll
        for (int i = 0; i < RT; i++) {
            ulonglong2 x = *(const ulonglong2*)&sX[i][k];
            fma2(acc[i], x.x, w01);
            fma2(acc[i], x.y, w23);
        }
    }
#pragma unroll
    for (int i = 0; i < RT; i++)
        g_h[(size_t)(base + i) * HD + j] = fmaxf(red2(acc[i]), 0.0f);
}

// ---------------- edge_gate = sigmoid(EF @ W_edge + b_edge) ----------------
__global__ void k_eg(const float* __restrict__ EF, const float* __restrict__ W,
                     const float* __restrict__ b) {
    __shared__ __align__(16) float sX[RE][FED];
    int base = blockIdx.x * RE;
    const float4* src = (const float4*)(EF + (size_t)base * FED);
    for (int i = threadIdx.x; i < RE * FED / 4; i += blockDim.x)
        ((float4*)sX)[i] = src[i];
    __syncthreads();
    int j = threadIdx.x;
    if (j >= HD) return;
    float acc[RE];
#pragma unroll
    for (int i = 0; i < RE; i++) acc[i] = b[j];
#pragma unroll
    for (int k = 0; k < FED; k++) {
        float w = W[k * HD + j];
#pragma unroll
        for (int i = 0; i < RE; i++) acc[i] += sX[i][k] * w;
    }
#pragma unroll
    for (int i = 0; i < RE; i++)
        g_eg[(size_t)(base + i) * HD + j] = sigf(acc[i]);
}

// ---------------- zero agg ----------------
__global__ void k_zero_agg() {
    int i = blockIdx.x * blockDim.x + threadIdx.x;
    if (i < NN * HD / 4) ((float4*)g_agg)[i] = make_float4(0.f, 0.f, 0.f, 0.f);
}

// ---------------- scatter: agg[dst] += eg[e] * h[src] ----------------
__global__ void k_scatter(const int* __restrict__ ei) {
    int idx = blockIdx.x * blockDim.x + threadIdx.x;
    if (idx >= NE * (HD / 4)) return;
    int e = idx / (HD / 4);
    int c = (idx - e * (HD / 4)) * 4;
    int s = ei[e];
    int d = ei[NE + e];
    float4 eg = *(const float4*)&g_eg[(size_t)e * HD + c];
    float4 hv = *(const float4*)&g_h[(size_t)s * HD + c];
    float* p = &g_agg[(size_t)d * HD + c];
    atomicAdd(p + 0, eg.x * hv.x);
    atomicAdd(p + 1, eg.y * hv.y);
    atomicAdd(p + 2, eg.z * hv.z);
    atomicAdd(p + 3, eg.w * hv.w);
}

// ---------------- fused tower + mix + GRU update  [FFMA2, paired weights] ----------------
__global__ void k_gru(const float* __restrict__ Wt,
                      const float* __restrict__ bmix,
                      const float* __restrict__ bz,
                      const float* __restrict__ br,
                      const float* __restrict__ bh) {
    __shared__ __align__(16) float sA[RT][HD];   // agg -> then m
    __shared__ __align__(16) float sT[RT][HD];   // tower out -> then r*h
    __shared__ __align__(16) float sH[RT][HD];   // h
    int base = blockIdx.x * RT;
    {
        const float4* a4 = (const float4*)(g_agg + (size_t)base * HD);
        const float4* h4 = (const float4*)(g_h + (size_t)base * HD);
        for (int i = threadIdx.x; i < RT * HD / 4; i += blockDim.x) {
            ((float4*)sA)[i] = a4[i];
            ((float4*)sH)[i] = h4[i];
        }
    }
    __syncthreads();

    int j = threadIdx.x;
    bool act = (j < HD);
    float zv[RT];

    // ---- tower mixing: sT[n][t*25+e] = sum_d sA[n][t*25+d] * Wt[t][d][e] ----
    if (act) {
        int t = j / DTW, e = j % DTW;
        const float* wt = Wt + (t * DTW) * DTW + e;
        float acc[RT];
#pragma unroll
        for (int i = 0; i < RT; i++) acc[i] = 0.0f;
#pragma unroll
        for (int d = 0; d < DTW; d++) {
            float w = wt[d * DTW];
            int kk = t * DTW + d;
#pragma unroll
            for (int i = 0; i < RT; i++) acc[i] += sA[i][kk] * w;
        }
#pragma unroll
        for (int i = 0; i < RT; i++) sT[i][j] = acc[i];
    }
    __syncthreads();

    // ---- m = relu(sT @ Wmix + bmix) -> sA ----
    if (act) {
        u64 acc[RT];
#pragma unroll
        for (int i = 0; i < RT; i++) acc[i] = pk2(bmix[j], 0.0f);
        for (int k = 0; k < HD; k += 4) {
            u64 w01 = g_Wmix_p[(k / 2) * HD + j];
            u64 w23 = g_Wmix_p[(k / 2 + 1) * HD + j];
#pragma unroll
            for (int i = 0; i < RT; i++) {
                ulonglong2 a = *(const ulonglong2*)&sT[i][k];
                fma2(acc[i], a.x, w01);
                fma2(acc[i], a.y, w23);
            }
        }
#pragma unroll
        for (int i = 0; i < RT; i++) sA[i][j] = fmaxf(red2(acc[i]), 0.0f);
    }
    __syncthreads();

    // ---- Z pass: z = sig(m@Wz + h@Uz + bz) ----
    if (act) {
        u64 acc[RT];
#pragma unroll
        for (int i = 0; i < RT; i++) acc[i] = pk2(bz[j], 0.0f);
        for (int k = 0; k < HD; k += 4) {
            u64 w01 = g_Wz_p[(k / 2) * HD + j];
            u64 w23 = g_Wz_p[(k / 2 + 1) * HD + j];
            u64 u01 = g_Uz_p[(k / 2) * HD + j];
            u64 u23 = g_Uz_p[(k / 2 + 1) * HD + j];
#pragma unroll
            for (int i = 0; i < RT; i++) {
                ulonglong2 m = *(const ulonglong2*)&sA[i][k];
                ulonglong2 h = *(const ulonglong2*)&sH[i][k];
                fma2(acc[i], m.x, w01);
                fma2(acc[i], m.y, w23);
                fma2(acc[i], h.x, u01);
                fma2(acc[i], h.y, u23);
            }
        }
#pragma unroll
        for (int i = 0; i < RT; i++) zv[i] = sigf(red2(acc[i]));
    }

    // ---- R pass: r = sig(m@Wr + h@Ur + br); sT = r*h ----
    if (act) {
        u64 acc[RT];
#pragma unroll
        for (int i = 0; i < RT; i++) acc[i] = pk2(br[j], 0.0f);
        for (int k = 0; k < HD; k += 4) {
            u64 w01 = g_Wr_p[(k / 2) * HD + j];
            u64 w23 = g_Wr_p[(k / 2 + 1) * HD + j];
            u64 u01 = g_Ur_p[(k / 2) * HD + j];
            u64 u23 = g_Ur_p[(k / 2 + 1) * HD + j];
#pragma unroll
            for (int i = 0; i < RT; i++) {
                ulonglong2 m = *(const ulonglong2*)&sA[i][k];
                ulonglong2 h = *(const ulonglong2*)&sH[i][k];
                fma2(acc[i], m.x, w01);
                fma2(acc[i], m.y, w23);
                fma2(acc[i], h.x, u01);
                fma2(acc[i], h.y, u23);
            }
        }
#pragma unroll
        for (int i = 0; i < RT; i++) {
            float r = sigf(red2(acc[i]));
            sT[i][j] = r * sH[i][j];
        }
    }
    __syncthreads();

    // ---- H pass: h~ = tanh(m@Wh + (r*h)@Uh + bh); h = (1-z)h + z*h~ ----
    if (act) {
        u64 acc[RT];
#pragma unroll
        for (int i = 0; i < RT; i++) acc[i] = pk2(bh[j], 0.0f);
        for (int k = 0; k < HD; k += 4) {
            u64 w01 = g_Wh_p[(k / 2) * HD + j];
            u64 w23 = g_Wh_p[(k / 2 + 1) * HD + j];
            u64 u01 = g_Uh_p[(k / 2) * HD + j];
            u64 u23 = g_Uh_p[(k / 2 + 1) * HD + j];
#pragma unroll
            for (int i = 0; i < RT; i++) {
                ulonglong2 m = *(const ulonglong2*)&sA[i][k];
                ulonglong2 t = *(const ulonglong2*)&sT[i][k];
                fma2(acc[i], m.x, w01);
                fma2(acc[i], m.y, w23);
                fma2(acc[i], t.x, u01);
                fma2(acc[i], t.y, u23);
            }
        }
#pragma unroll
        for (int i = 0; i < RT; i++) {
            float ht = tanhf(red2(acc[i]));
            g_h[(size_t)(base + i) * HD + j] = (1.0f - zv[i]) * sH[i][j] + zv[i] * ht;
        }
    }
}

// ---------------- init readout scratch ----------------
__global__ void k_init_small() {
    int t = blockIdx.x * blockDim.x + threadIdx.x;
    for (int i = t; i < NG * HD; i += gridDim.x * blockDim.x) g_gfeat[i] = 0.0f;
    if (t < NG) { g_denom[t] = 0.0f; g_smax[t] = enc_f(-INFINITY); }
}

// ---------------- score + segment max ----------------
__global__ void k_score(const float* __restrict__ Ws, const float* __restrict__ bs,
                        const int* __restrict__ bv) {
    int n = blockIdx.x * 8 + (threadIdx.x >> 5);
    if (n >= NN) return;
    int lane = threadIdx.x & 31;
    float acc = 0.0f;
    for (int k = lane; k < HD; k += 32) acc += g_h[(size_t)n * HD + k] * Ws[k];
#pragma unroll
    for (int o = 16; o; o >>= 1) acc += __shfl_xor_sync(0xffffffffu, acc, o);
    if (lane == 0) {
        float s = acc + bs[0];
        g_score[n] = s;
        atomicMax(&g_smax[bv[n]], enc_f(s));
    }
}

// ---------------- exp + segment sum (run-length aggregated) ----------------
__global__ void k_exp(const int* __restrict__ bv) {
    int n0 = (blockIdx.x * blockDim.x + threadIdx.x) * 16;
    if (n0 >= NN) return;
    int end = n0 + 16; if (end > NN) end = NN;
    int cb = bv[n0];
    float mx = dec_f(g_smax[cb]);
    float run = 0.0f;
    for (int n = n0; n < end; n++) {
        int b = bv[n];
        if (b != cb) {
            atomicAdd(&g_denom[cb], run);
            run = 0.0f; cb = b; mx = dec_f(g_smax[b]);
        }
        float ex = __expf(g_score[n] - mx);
        g_ex[n] = ex;
        run += ex;
    }
    atomicAdd(&g_denom[cb], run);
}

// ---------------- feat = h@W_feat + b_feat; g[b] += alpha*feat  [FFMA2] -------
__global__ void k_feat(const float* __restrict__ bf, const int* __restrict__ bv) {
    __shared__ __align__(16) float sHt[RT][HD];
    __shared__ float sAl[RT];
    __shared__ int   sB[RT];
    int base = blockIdx.x * RT;
    {
        const float4* h4 = (const float4*)(g_h + (size_t)base * HD);
        for (int i = threadIdx.x; i < RT * HD / 4; i += blockDim.x)
            ((float4*)sHt)[i] = h4[i];
    }
    if (threadIdx.x < RT) {
        int n = base + threadIdx.x;
        int b = bv[n];
        sB[threadIdx.x] = b;
        sAl[threadIdx.x] = g_ex[n] / g_denom[b];
    }
    __syncthreads();
    int j = threadIdx.x;
    if (j >= HD) return;
    u64 acc[RT];
#pragma unroll
    for (int i = 0; i < RT; i++) acc[i] = pk2(bf[j], 0.0f);
    for (int k = 0; k < HD; k += 4) {
        u64 w01 = g_Wf_p[(k / 2) * HD + j];
        u64 w23 = g_Wf_p[(k / 2 + 1) * HD + j];
#pragma unroll
        for (int i = 0; i < RT; i++) {
            ulonglong2 h = *(const ulonglong2*)&sHt[i][k];
            fma2(acc[i], h.x, w01);
            fma2(acc[i], h.y, w23);
        }
    }
    // run-length aggregate atomics (batch_vector is sorted)
    float run = 0.0f;
    int cb = sB[0];
#pragma unroll
    for (int i = 0; i < RT; i++) {
        if (sB[i] != cb) {
            atomicAdd(&g_gfeat[cb * HD + j], run);
            run = 0.0f; cb = sB[i];
        }
        run += sAl[i] * red2(acc[i]);
    }
    atomicAdd(&g_gfeat[cb * HD + j], run);
}

// ---------------- readout MLP: out = relu(g@W_r1+b_r1)@W_out + b_out ----------------
__global__ void k_readout(const float* __restrict__ Wr1, const float* __restrict__ br1,
                          const float* __restrict__ Wout, const float* __restrict__ bout,
                          float* __restrict__ out) {
    __shared__ float sG[HD];
    __shared__ float sRed[256];
    int g = blockIdx.x;
    for (int k = threadIdx.x; k < HD; k += blockDim.x) sG[k] = g_gfeat[g * HD + k];
    __syncthreads();
    float p = 0.0f;
    int j = threadIdx.x;
    if (j < HD) {
        float acc = br1[j];
        for (int k = 0; k < HD; k++) acc += sG[k] * Wr1[k * HD + j];
        p = fmaxf(acc, 0.0f) * Wout[j];
    }
    sRed[threadIdx.x] = p;
    __syncthreads();
    for (int s = 128; s; s >>= 1) {
        if (threadIdx.x < s) sRed[threadIdx.x] += sRed[threadIdx.x + s];
        __syncthreads();
    }
    if (threadIdx.x == 0) out[g] = sRed[0] + bout[0];
}

// ---------------- launch ----------------
extern "C" void kernel_launch(void* const* d_in, const int* in_sizes, int n_in,
                              void* d_out, int out_size) {
    const float* node_features = (const float*)d_in[0];
    const float* edge_features = (const float*)d_in[1];
    const int*   edge_index    = (const int*)d_in[2];
    const int*   batch_vector  = (const int*)d_in[3];
    const float* W_in   = (const float*)d_in[4];
    const float* b_in   = (const float*)d_in[5];
    const float* W_edge = (const float*)d_in[6];
    const float* b_edge = (const float*)d_in[7];
    const float* W_tower= (const float*)d_in[8];
    const float* W_mix  = (const float*)d_in[9];
    const float* b_mix  = (const float*)d_in[10];
    const float* Wz = (const float*)d_in[11];
    const float* Uz = (const float*)d_in[12];
    const float* bz = (const float*)d_in[13];
    const float* Wr = (const float*)d_in[14];
    const float* Ur = (const float*)d_in[15];
    const float* br = (const float*)d_in[16];
    const float* Wh = (const float*)d_in[17];
    const float* Uh = (const float*)d_in[18];
    const float* bh = (const float*)d_in[19];
    const float* W_score = (const float*)d_in[20];
    const float* b_score = (const float*)d_in[21];
    const float* W_feat  = (const float*)d_in[22];
    const float* b_feat  = (const float*)d_in[23];
    const float* W_r1    = (const float*)d_in[24];
    const float* b_r1    = (const float*)d_in[25];
    const float* W_out   = (const float*)d_in[26];
    const float* b_out   = (const float*)d_in[27];
    float* out = (float*)d_out;

    // one-time (per launch) weight pair-packing
    int nb = ((HD / 2) * HD + 255) / 256;
    k_pack<<<nb, 256>>>(W_mix, HD, HD, 0);
    k_pack<<<nb, 256>>>(Wz,    HD, HD, 1);
    k_pack<<<nb, 256>>>(Uz,    HD, HD, 2);
    k_pack<<<nb, 256>>>(Wr,    HD, HD, 3);
    k_pack<<<nb, 256>>>(Ur,    HD, HD, 4);
    k_pack<<<nb, 256>>>(Wh,    HD, HD, 5);
    k_pack<<<nb, 256>>>(Uh,    HD, HD, 6);
    k_pack<<<nb, 256>>>(W_feat,HD, HD, 7);
    k_pack<<<((FND / 2) * HD + 255) / 256, 256>>>(W_in, FND, HD, 8);

    k_h0<<<NN / RT, 224>>>(node_features, b_in);
    k_eg<<<NE / RE, 224>>>(edge_features, W_edge, b_edge);

    for (int s = 0; s < NSTEPS; s++) {
        k_zero_agg<<<(NN * HD / 4 + 255) / 256, 256>>>();
        k_scatter<<<(NE * (HD / 4) + 255) / 256, 256>>>(edge_index);
        k_gru<<<NN / RT, 224>>>(W_tower, b_mix, bz, br, bh);
    }

    k_init_small<<<50, 256>>>();
    k_score<<<(NN + 7) / 8, 256>>>(W_score, b_score, batch_vector);
    k_exp<<<(NN / 16 + 255) / 256, 256>>>(batch_vector);
    k_feat<<<NN / RT, 224>>>(b_feat, batch_vector);
    k_readout<<<NG, 256>>>(W_r1, b_r1, W_out, b_out, out);
}

// round 5
// speedup vs baseline: 1.9762x; 1.6249x over previous
#include <cuda_runtime.h>
#include <math.h>

#define NN  100000
#define NE  800000
#define FND 128
#define FED 16
#define HD  200
#define HP  224    // padded hidden (multiple of 16/32)
#define DTW 25
#define NG  64
#define NSTEPS 3
#define RT  16     // node rows per block (scalar kernels)
#define RE  32     // edge rows per block

#define BM 128
#define BN 64
#define BK 16

typedef unsigned long long u64;

// ---------------- scratch (static device memory; no allocation) ----------------
__device__ float     g_h[(size_t)NN * HP];     // hidden state (padded, pads finite)
__device__ float     g_m[(size_t)NN * HP];     // message m
__device__ float     g_t[(size_t)NN * HP];     // tower output
__device__ float     g_rh[(size_t)NN * HP];    // r * h
__device__ float     g_z[(size_t)NN * HP];     // z gate
__device__ float     g_agg[(size_t)NN * HD];
__device__ float     g_eg[(size_t)NE * HD];
__device__ float     g_score[NN];
__device__ float     g_ex[NN];
__device__ unsigned  g_smax[NG];
__device__ float     g_denom[NG];
__device__ float     g_gfeat[NG * HD];
// padded, tf32-rounded weights (zero-init pads persist — never written)
__device__ float     g_Win_pad[FND * 256];      // [128][256]
__device__ float     g_Wmix_pad[HP * 256];      // [224][256] (rows 200-223 zero)
__device__ float     g_Wzr[(2 * HP) * 512];     // [[Wz|Wr],[Uz|Ur]] [448][512]
__device__ float     g_Whh[(2 * HP) * 256];     // [Wh;Uh] [448][256]
__device__ float     g_bin_pad[256];
__device__ float     g_bmix_pad[256];
__device__ float     g_bzr[512];
__device__ float     g_bh_pad[256];
// pair-interleaved W_feat for scalar feat kernel
__device__ u64       g_Wf_p[(HD / 2) * HD];

__device__ __forceinline__ float sigf(float x) { return 1.0f / (1.0f + __expf(-x)); }
__device__ __forceinline__ float tf32f(float x) {
    unsigned u; asm("cvt.rna.tf32.f32 %0,%1;" : "=r"(u) : "f"(x));
    return __uint_as_float(u);
}
__device__ __forceinline__ u64 pk2(float lo, float hi) {
    u64 r; asm("mov.b64 %0,{%1,%2};" : "=l"(r) : "f"(lo), "f"(hi)); return r;
}
__device__ __forceinline__ void fma2(u64& d, u64 a, u64 b) {
    asm("fma.rn.f32x2 %0,%1,%2,%0;" : "+l"(d) : "l"(a), "l"(b));
}
__device__ __forceinline__ float red2(u64 v) {
    float a, b; asm("mov.b64 {%0,%1},%2;" : "=f"(a), "=f"(b) : "l"(v)); return a + b;
}
__device__ __forceinline__ unsigned enc_f(float f) {
    unsigned u = __float_as_uint(f);
    return (u & 0x80000000u) ? ~u : (u | 0x80000000u);
}
__device__ __forceinline__ float dec_f(unsigned u) {
    u = (u & 0x80000000u) ? (u & 0x7FFFFFFFu) : ~u;
    return __uint_as_float(u);
}

// ---------------- weight pack: pad + tf32-round (pads stay zero) ----------------
__global__ void k_pack_all(const float* __restrict__ Win, const float* __restrict__ bin,
                           const float* __restrict__ Wmix, const float* __restrict__ bmix,
                           const float* __restrict__ Wz, const float* __restrict__ Uz,
                           const float* __restrict__ bz,
                           const float* __restrict__ Wr, const float* __restrict__ Ur,
                           const float* __restrict__ br,
                           const float* __restrict__ Wh, const float* __restrict__ Uh,
                           const float* __restrict__ bh,
                           const float* __restrict__ Wf) {
    int idx = blockIdx.x * blockDim.x + threadIdx.x;
    if (idx < HD * HD) {
        int k = idx / HD, j = idx - k * HD;
        g_Wzr[k * 512 + j]              = tf32f(Wz[idx]);
        g_Wzr[k * 512 + 256 + j]        = tf32f(Wr[idx]);
        g_Wzr[(HP + k) * 512 + j]       = tf32f(Uz[idx]);
        g_Wzr[(HP + k) * 512 + 256 + j] = tf32f(Ur[idx]);
        g_Whh[k * 256 + j]              = tf32f(Wh[idx]);
        g_Whh[(HP + k) * 256 + j]       = tf32f(Uh[idx]);
        g_Wmix_pad[k * 256 + j]         = tf32f(Wmix[idx]);
    }
    if (idx < FND * HD) {
        int k = idx / HD, j = idx - k * HD;
        g_Win_pad[k * 256 + j] = tf32f(Win[idx]);
    }
    if (idx < (HD / 2) * HD) {
        int p = idx / HD, j = idx - p * HD;
        g_Wf_p[idx] = pk2(Wf[(2 * p) * HD + j], Wf[(2 * p + 1) * HD + j]);
    }
    if (idx < HD) {
        g_bin_pad[idx]  = bin[idx];
        g_bmix_pad[idx] = bmix[idx];
        g_bzr[idx]       = bz[idx];
        g_bzr[256 + idx] = br[idx];
        g_bh_pad[idx]   = bh[idx];
    }
}

// ---------------- tf32 tensor-core GEMM with fused epilogues ----------------
// MODE 0: h = relu(X @ Win + bin)                    K=128
// MODE 1: m = relu(t @ Wmix + bmix)                  K=224
// MODE 2: [z|r] = sig([m|h] @ Wzr + bzr); rh = r*h   K=448, Nout=512
// MODE 3: h = (1-z)h + z*tanh([m|rh] @ Whh + bh)     K=448
template<int MODE, int KC_TOT, int KC1, int SA, int SB>
__global__ void __launch_bounds__(256) k_gemm(const float* __restrict__ Aext) {
    __shared__ __align__(16) float sA[2][BM][BK + 4];   // stride 20: conflict-free frags
    __shared__ __align__(16) float sB[2][BK][BN + 8];   // stride 72: conflict-free frags
    const int t = threadIdx.x;
    const int bm = blockIdx.x * BM;
    const int n0 = blockIdx.y * BN;
    const int lane = t & 31, w = t >> 5;
    const int wr = (w >> 1) * 32;     // 4 row-warps
    const int wc = (w & 1) * 32;      // 2 col-warps

    const float* Bw;
    const float* bias;
    if (MODE == 0) { Bw = g_Win_pad;  bias = g_bin_pad; }
    else if (MODE == 1) { Bw = g_Wmix_pad; bias = g_bmix_pad; }
    else if (MODE == 2) { Bw = g_Wzr;  bias = g_bzr; }
    else { Bw = g_Whh;  bias = g_bh_pad; }

    float4 ra0, ra1, rb0;
    const int ar0 = t >> 2, akc = (t & 3) * 4;  // A stage: 2 float4/thread
    const int ar1 = ar0 + 64;
    const int brk = t >> 4, bcc = (t & 15) * 4; // B stage: 1 float4/thread

    auto ldg = [&](int c) {
        const float* Ap; int koff;
        if (c < KC1) {
            Ap = (MODE == 0) ? Aext : ((MODE == 1) ? g_t : g_m);
            koff = c * BK;
        } else {
            Ap = (MODE == 2) ? g_h : g_rh;
            koff = (c - KC1) * BK;
        }
        int g0 = bm + ar0, g1 = bm + ar1;
        ra0 = (g0 < NN) ? *(const float4*)(Ap + (size_t)g0 * SA + koff + akc)
                        : make_float4(0.f, 0.f, 0.f, 0.f);
        ra1 = (g1 < NN) ? *(const float4*)(Ap + (size_t)g1 * SA + koff + akc)
                        : make_float4(0.f, 0.f, 0.f, 0.f);
        rb0 = *(const float4*)(Bw + (size_t)(c * BK + brk) * SB + n0 + bcc);
    };
    auto sts = [&](int buf) {
        *(float4*)&sA[buf][ar0][akc] =
            make_float4(tf32f(ra0.x), tf32f(ra0.y), tf32f(ra0.z), tf32f(ra0.w));
        *(float4*)&sA[buf][ar1][akc] =
            make_float4(tf32f(ra1.x), tf32f(ra1.y), tf32f(ra1.z), tf32f(ra1.w));
        *(float4*)&sB[buf][brk][bcc] = rb0;    // weights pre-rounded
    };

    float acc[2][4][4];
#pragma unroll
    for (int rt = 0; rt < 2; rt++)
#pragma unroll
        for (int ct = 0; ct < 4; ct++)
#pragma unroll
            for (int e = 0; e < 4; e++) acc[rt][ct][e] = 0.0f;

    auto compute = [&](int buf) {
#pragma unroll
        for (int ks = 0; ks < BK; ks += 8) {
            unsigned a[2][4], b[4][2];
            int kk = ks + (lane & 3);
            int q = lane >> 2;
#pragma unroll
            for (int rt = 0; rt < 2; rt++) {
                int r0 = wr + rt * 16 + q;
                a[rt][0] = __float_as_uint(sA[buf][r0][kk]);
                a[rt][1] = __float_as_uint(sA[buf][r0 + 8][kk]);
                a[rt][2] = __float_as_uint(sA[buf][r0][kk + 4]);
                a[rt][3] = __float_as_uint(sA[buf][r0 + 8][kk + 4]);
            }
#pragma unroll
            for (int ct = 0; ct < 4; ct++) {
                int cn = wc + ct * 8 + q;
                b[ct][0] = __float_as_uint(sB[buf][kk][cn]);
                b[ct][1] = __float_as_uint(sB[buf][kk + 4][cn]);
            }
#pragma unroll
            for (int rt = 0; rt < 2; rt++)
#pragma unroll
                for (int ct = 0; ct < 4; ct++)
                    asm volatile(
                        "mma.sync.aligned.m16n8k8.row.col.f32.tf32.tf32.f32 "
                        "{%0,%1,%2,%3},{%4,%5,%6,%7},{%8,%9},{%0,%1,%2,%3};"
                        : "+f"(acc[rt][ct][0]), "+f"(acc[rt][ct][1]),
                          "+f"(acc[rt][ct][2]), "+f"(acc[rt][ct][3])
                        : "r"(a[rt][0]), "r"(a[rt][1]), "r"(a[rt][2]), "r"(a[rt][3]),
                          "r"(b[ct][0]), "r"(b[ct][1]));
        }
    };

    ldg(0); sts(0);
    __syncthreads();
#pragma unroll 1
    for (int c = 0; c < KC_TOT; c++) {
        int buf = c & 1;
        if (c + 1 < KC_TOT) ldg(c + 1);
        compute(buf);
        if (c + 1 < KC_TOT) { sts(buf ^ 1); __syncthreads(); }
    }

    // ---- epilogue ----
#pragma unroll
    for (int rt = 0; rt < 2; rt++) {
        int r_lo = wr + rt * 16 + (lane >> 2);
#pragma unroll
        for (int half = 0; half < 2; half++) {
            int gr = bm + r_lo + half * 8;
            if (gr >= NN) continue;
#pragma unroll
            for (int ct = 0; ct < 4; ct++) {
#pragma unroll
                for (int e = 0; e < 2; e++) {
                    int cn = wc + ct * 8 + (lane & 3) * 2 + e;
                    int gn = n0 + cn;
                    float v = acc[rt][ct][half * 2 + e] + bias[gn];
                    if (MODE == 0) {
                        if (gn < HP) g_h[(size_t)gr * HP + gn] = fmaxf(v, 0.0f);
                    } else if (MODE == 1) {
                        if (gn < HP) g_m[(size_t)gr * HP + gn] = fmaxf(v, 0.0f);
                    } else if (MODE == 2) {
                        if (gn < 256) {
                            if (gn < HP) g_z[(size_t)gr * HP + gn] = sigf(v);
                        } else {
                            int cc = gn - 256;
                            if (cc < HP) {
                                float hv = g_h[(size_t)gr * HP + cc];
                                g_rh[(size_t)gr * HP + cc] = sigf(v) * hv;
                            }
                        }
                    } else {
                        if (gn < HP) {
                            float hprev = g_h[(size_t)gr * HP + gn];
                            float zz = g_z[(size_t)gr * HP + gn];
                            g_h[(size_t)gr * HP + gn] =
                                (1.0f - zz) * hprev + zz * tanhf(v);
                        }
                    }
                }
            }
        }
    }
}

// ---------------- edge_gate = sigmoid(EF @ W_edge + b_edge) ----------------
__global__ void k_eg(const float* __restrict__ EF, const float* __restrict__ W,
                     const float* __restrict__ b) {
    __shared__ __align__(16) float sX[RE][FED];
    int base = blockIdx.x * RE;
    const float4* src = (const float4*)(EF + (size_t)base * FED);
    for (int i = threadIdx.x; i < RE * FED / 4; i += blockDim.x)
        ((float4*)sX)[i] = src[i];
    __syncthreads();
    int j = threadIdx.x;
    if (j >= HD) return;
    float acc[RE];
#pragma unroll
    for (int i = 0; i < RE; i++) acc[i] = b[j];
#pragma unroll
    for (int k = 0; k < FED; k++) {
        float w = W[k * HD + j];
#pragma unroll
        for (int i = 0; i < RE; i++) acc[i] += sX[i][k] * w;
    }
#pragma unroll
    for (int i = 0; i < RE; i++)
        g_eg[(size_t)(base + i) * HD + j] = sigf(acc[i]);
}

// ---------------- zero agg ----------------
__global__ void k_zero_agg() {
    int i = blockIdx.x * blockDim.x + threadIdx.x;
    if (i < NN * HD / 4) ((float4*)g_agg)[i] = make_float4(0.f, 0.f, 0.f, 0.f);
}

// ---------------- scatter: agg[dst] += eg[e] * h[src]  (h stride HP) ----------------
__global__ void k_scatter(const int* __restrict__ ei) {
    int idx = blockIdx.x * blockDim.x + threadIdx.x;
    if (idx >= NE * (HD / 4)) return;
    int e = idx / (HD / 4);
    int c = (idx - e * (HD / 4)) * 4;
    int s = ei[e];
    int d = ei[NE + e];
    float4 eg = *(const float4*)&g_eg[(size_t)e * HD + c];
    float4 hv = *(const float4*)&g_h[(size_t)s * HP + c];
    float* p = &g_agg[(size_t)d * HD + c];
    atomicAdd(p + 0, eg.x * hv.x);
    atomicAdd(p + 1, eg.y * hv.y);
    atomicAdd(p + 2, eg.z * hv.z);
    atomicAdd(p + 3, eg.w * hv.w);
}

// ---------------- tower mixing -> g_t (padded, zeros in pad cols) ----------------
__global__ void k_tower(const float* __restrict__ Wt) {
    __shared__ __align__(16) float sA[RT][HD];
    int base = blockIdx.x * RT;
    {
        const float4* a4 = (const float4*)(g_agg + (size_t)base * HD);
        for (int i = threadIdx.x; i < RT * HD / 4; i += blockDim.x)
            ((float4*)sA)[i] = a4[i];
    }
    __syncthreads();
    int j = threadIdx.x;   // blockDim = HP = 224
    if (j < HD) {
        int tt = j / DTW, e = j % DTW;
        const float* wt = Wt + (tt * DTW) * DTW + e;
        float acc[RT];
#pragma unroll
        for (int i = 0; i < RT; i++) acc[i] = 0.0f;
#pragma unroll
        for (int d = 0; d < DTW; d++) {
            float w = wt[d * DTW];
            int kk = tt * DTW + d;
#pragma unroll
            for (int i = 0; i < RT; i++) acc[i] += sA[i][kk] * w;
        }
#pragma unroll
        for (int i = 0; i < RT; i++) g_t[(size_t)(base + i) * HP + j] = acc[i];
    } else {
#pragma unroll
        for (int i = 0; i < RT; i++) g_t[(size_t)(base + i) * HP + j] = 0.0f;
    }
}

// ---------------- init readout scratch ----------------
__global__ void k_init_small() {
    int t = blockIdx.x * blockDim.x + threadIdx.x;
    for (int i = t; i < NG * HD; i += gridDim.x * blockDim.x) g_gfeat[i] = 0.0f;
    if (t < NG) { g_denom[t] = 0.0f; g_smax[t] = enc_f(-INFINITY); }
}

// ---------------- score + segment max ----------------
__global__ void k_score(const float* __restrict__ Ws, const float* __restrict__ bs,
                        const int* __restrict__ bv) {
    int n = blockIdx.x * 8 + (threadIdx.x >> 5);
    if (n >= NN) return;
    int lane = threadIdx.x & 31;
    float acc = 0.0f;
    for (int k = lane; k < HD; k += 32) acc += g_h[(size_t)n * HP + k] * Ws[k];
#pragma unroll
    for (int o = 16; o; o >>= 1) acc += __shfl_xor_sync(0xffffffffu, acc, o);
    if (lane == 0) {
        float s = acc + bs[0];
        g_score[n] = s;
        atomicMax(&g_smax[bv[n]], enc_f(s));
    }
}

// ---------------- exp + segment sum ----------------
__global__ void k_exp(const int* __restrict__ bv) {
    int n0 = (blockIdx.x * blockDim.x + threadIdx.x) * 16;
    if (n0 >= NN) return;
    int end = n0 + 16; if (end > NN) end = NN;
    int cb = bv[n0];
    float mx = dec_f(g_smax[cb]);
    float run = 0.0f;
    for (int n = n0; n < end; n++) {
        int b = bv[n];
        if (b != cb) {
            atomicAdd(&g_denom[cb], run);
            run = 0.0f; cb = b; mx = dec_f(g_smax[b]);
        }
        float ex = __expf(g_score[n] - mx);
        g_ex[n] = ex;
        run += ex;
    }
    atomicAdd(&g_denom[cb], run);
}

// ---------------- feat = h@W_feat + b_feat; g[b] += alpha*feat ----------------
__global__ void k_feat(const float* __restrict__ bf, const int* __restrict__ bv) {
    __shared__ __align__(16) float sHt[RT][HD];
    __shared__ float sAl[RT];
    __shared__ int   sB[RT];
    int base = blockIdx.x * RT;
    for (int i = threadIdx.x; i < RT * (HD / 4); i += blockDim.x) {
        int row = i / (HD / 4), c4 = i % (HD / 4);
        *(float4*)&sHt[row][c4 * 4] =
            *(const float4*)&g_h[(size_t)(base + row) * HP + c4 * 4];
    }
    if (threadIdx.x < RT) {
        int n = base + threadIdx.x;
        int b = bv[n];
        sB[threadIdx.x] = b;
        sAl[threadIdx.x] = g_ex[n] / g_denom[b];
    }
    __syncthreads();
    int j = threadIdx.x;
    if (j >= HD) return;
    u64 acc[RT];
#pragma unroll
    for (int i = 0; i < RT; i++) acc[i] = pk2(bf[j], 0.0f);
    for (int k = 0; k < HD; k += 4) {
        u64 w01 = g_Wf_p[(k / 2) * HD + j];
        u64 w23 = g_Wf_p[(k / 2 + 1) * HD + j];
#pragma unroll
        for (int i = 0; i < RT; i++) {
            ulonglong2 h = *(const ulonglong2*)&sHt[i][k];
            fma2(acc[i], h.x, w01);
            fma2(acc[i], h.y, w23);
        }
    }
    float run = 0.0f;
    int cb = sB[0];
#pragma unroll
    for (int i = 0; i < RT; i++) {
        if (sB[i] != cb) {
            atomicAdd(&g_gfeat[cb * HD + j], run);
            run = 0.0f; cb = sB[i];
        }
        run += sAl[i] * red2(acc[i]);
    }
    atomicAdd(&g_gfeat[cb * HD + j], run);
}

// ---------------- readout MLP ----------------
__global__ void k_readout(const float* __restrict__ Wr1, const float* __restrict__ br1,
                          const float* __restrict__ Wout, const float* __restrict__ bout,
                          float* __restrict__ out) {
    __shared__ float sG[HD];
    __shared__ float sRed[256];
    int g = blockIdx.x;
    for (int k = threadIdx.x; k < HD; k += blockDim.x) sG[k] = g_gfeat[g * HD + k];
    __syncthreads();
    float p = 0.0f;
    int j = threadIdx.x;
    if (j < HD) {
        float acc = br1[j];
        for (int k = 0; k < HD; k++) acc += sG[k] * Wr1[k * HD + j];
        p = fmaxf(acc, 0.0f) * Wout[j];
    }
    sRed[threadIdx.x] = p;
    __syncthreads();
    for (int s = 128; s; s >>= 1) {
        if (threadIdx.x < s) sRed[threadIdx.x] += sRed[threadIdx.x + s];
        __syncthreads();
    }
    if (threadIdx.x == 0) out[g] = sRed[0] + bout[0];
}

// ---------------- launch ----------------
extern "C" void kernel_launch(void* const* d_in, const int* in_sizes, int n_in,
                              void* d_out, int out_size) {
    const float* node_features = (const float*)d_in[0];
    const float* edge_features = (const float*)d_in[1];
    const int*   edge_index    = (const int*)d_in[2];
    const int*   batch_vector  = (const int*)d_in[3];
    const float* W_in   = (const float*)d_in[4];
    const float* b_in   = (const float*)d_in[5];
    const float* W_edge = (const float*)d_in[6];
    const float* b_edge = (const float*)d_in[7];
    const float* W_tower= (const float*)d_in[8];
    const float* W_mix  = (const float*)d_in[9];
    const float* b_mix  = (const float*)d_in[10];
    const float* Wz = (const float*)d_in[11];
    const float* Uz = (const float*)d_in[12];
    const float* bz = (const float*)d_in[13];
    const float* Wr = (const float*)d_in[14];
    const float* Ur = (const float*)d_in[15];
    const float* br = (const float*)d_in[16];
    const float* Wh = (const float*)d_in[17];
    const float* Uh = (const float*)d_in[18];
    const float* bh = (const float*)d_in[19];
    const float* W_score = (const float*)d_in[20];
    const float* b_score = (const float*)d_in[21];
    const float* W_feat  = (const float*)d_in[22];
    const float* b_feat  = (const float*)d_in[23];
    const float* W_r1    = (const float*)d_in[24];
    const float* b_r1    = (const float*)d_in[25];
    const float* W_out   = (const float*)d_in[26];
    const float* b_out   = (const float*)d_in[27];
    float* out = (float*)d_out;

    k_pack_all<<<(HD * HD + 255) / 256, 256>>>(
        W_in, b_in, W_mix, b_mix, Wz, Uz, bz, Wr, Ur, br, Wh, Uh, bh, W_feat);

    const int GX = (NN + BM - 1) / BM;   // 782
    // h0 = relu(X @ Win)
    k_gemm<0, FND / BK, FND / BK, FND, 256><<<dim3(GX, 4), 256>>>(node_features);
    k_eg<<<NE / RE, 224>>>(edge_features, W_edge, b_edge);

    for (int s = 0; s < NSTEPS; s++) {
        k_zero_agg<<<(NN * HD / 4 + 255) / 256, 256>>>();
        k_scatter<<<(NE * (HD / 4) + 255) / 256, 256>>>(edge_index);
        k_tower<<<NN / RT, HP>>>(W_tower);
        k_gemm<1, HP / BK, HP / BK, HP, 256><<<dim3(GX, 4), 256>>>(nullptr);
        k_gemm<2, 2 * HP / BK, HP / BK, HP, 512><<<dim3(GX, 8), 256>>>(nullptr);
        k_gemm<3, 2 * HP / BK, HP / BK, HP, 256><<<dim3(GX, 4), 256>>>(nullptr);
    }

    k_init_small<<<50, 256>>>();
    k_score<<<(NN + 7) / 8, 256>>>(W_score, b_score, batch_vector);
    k_exp<<<(NN / 16 + 255) / 256, 256>>>(batch_vector);
    k_feat<<<NN / RT, 224>>>(b_feat, batch_vector);
    k_readout<<<NG, 256>>>(W_r1, b_r1, W_out, b_out, out);
}

// round 6
// speedup vs baseline: 2.1817x; 1.1040x over previous
#include <cuda_runtime.h>
#include <cuda_fp16.h>
#include <math.h>

#define NN  100000
#define NE  800000
#define FND 128
#define FED 16
#define HD  200
#define HP  224    // padded hidden (multiple of 16/32)
#define DTW 25
#define NG  64
#define NSTEPS 3
#define RT  16
#define RE  32

#define BM 64
#define BN 256
#define BK 16

typedef unsigned long long u64;

// ---------------- scratch (static device memory; no allocation) ----------------
__device__ float     g_h[(size_t)NN * HP];
__device__ float     g_m[(size_t)NN * HP];
__device__ float     g_rh[(size_t)NN * HP];
__device__ float     g_z[(size_t)NN * HP];
__device__ float     g_agg[(size_t)NN * HP];
__device__ __half    g_eg[(size_t)NE * HD];
__device__ float     g_score[NN];
__device__ float     g_ex[NN];
__device__ unsigned  g_smax[NG];
__device__ float     g_denom[NG];
__device__ float     g_gfeat[NG * HD];
// padded, tf32-rounded weights (zero-init pads persist — never written)
__device__ float     g_Win_pad[FND * 256];      // [128][256]
__device__ float     g_Wcomb[HP * 256];         // blockdiag(Wt)@Wmix, rows/cols padded
__device__ float     g_Wzr[(2 * HP) * 512];     // [[Wz|Wr],[Uz|Ur]] [448][512]
__device__ float     g_Whh[(2 * HP) * 256];     // [Wh;Uh] [448][256]
__device__ float     g_bin_pad[256];
__device__ float     g_bmix_pad[256];
__device__ float     g_bzr[512];
__device__ float     g_bh_pad[256];
__device__ u64       g_Wf_p[(HD / 2) * HD];

__device__ __forceinline__ float sigf(float x) { return 1.0f / (1.0f + __expf(-x)); }
__device__ __forceinline__ float tf32f(float x) {
    unsigned u; asm("cvt.rna.tf32.f32 %0,%1;" : "=r"(u) : "f"(x));
    return __uint_as_float(u);
}
__device__ __forceinline__ u64 pk2(float lo, float hi) {
    u64 r; asm("mov.b64 %0,{%1,%2};" : "=l"(r) : "f"(lo), "f"(hi)); return r;
}
__device__ __forceinline__ void fma2(u64& d, u64 a, u64 b) {
    asm("fma.rn.f32x2 %0,%1,%2,%0;" : "+l"(d) : "l"(a), "l"(b));
}
__device__ __forceinline__ float red2(u64 v) {
    float a, b; asm("mov.b64 {%0,%1},%2;" : "=f"(a), "=f"(b) : "l"(v)); return a + b;
}
__device__ __forceinline__ unsigned enc_f(float f) {
    unsigned u = __float_as_uint(f);
    return (u & 0x80000000u) ? ~u : (u | 0x80000000u);
}
__device__ __forceinline__ float dec_f(unsigned u) {
    u = (u & 0x80000000u) ? (u & 0x7FFFFFFFu) : ~u;
    return __uint_as_float(u);
}

// ---------------- weight pack: pad + tf32 round + tower-fold ----------------
__global__ void k_pack_all(const float* __restrict__ Win, const float* __restrict__ bin,
                           const float* __restrict__ Wt,
                           const float* __restrict__ Wmix, const float* __restrict__ bmix,
                           const float* __restrict__ Wz, const float* __restrict__ Uz,
                           const float* __restrict__ bz,
                           const float* __restrict__ Wr, const float* __restrict__ Ur,
                           const float* __restrict__ br,
                           const float* __restrict__ Wh, const float* __restrict__ Uh,
                           const float* __restrict__ bh,
                           const float* __restrict__ Wf) {
    int idx = blockIdx.x * blockDim.x + threadIdx.x;
    if (idx < HD * HD) {
        int k = idx / HD, j = idx - k * HD;
        g_Wzr[k * 512 + j]              = tf32f(Wz[idx]);
        g_Wzr[k * 512 + 256 + j]        = tf32f(Wr[idx]);
        g_Wzr[(HP + k) * 512 + j]       = tf32f(Uz[idx]);
        g_Wzr[(HP + k) * 512 + 256 + j] = tf32f(Ur[idx]);
        g_Whh[k * 256 + j]              = tf32f(Wh[idx]);
        g_Whh[(HP + k) * 256 + j]       = tf32f(Uh[idx]);
        // tower fold: Wcomb[t*25+d][j] = sum_e Wt[t][d][e] * Wmix[t*25+e][j]
        int tt = k / DTW, d = k - tt * DTW;
        float s = 0.0f;
#pragma unroll
        for (int e = 0; e < DTW; e++)
            s += Wt[tt * DTW * DTW + d * DTW + e] * Wmix[(tt * DTW + e) * HD + j];
        g_Wcomb[k * 256 + j] = tf32f(s);
    }
    if (idx < FND * HD) {
        int k = idx / HD, j = idx - k * HD;
        g_Win_pad[k * 256 + j] = tf32f(Win[idx]);
    }
    if (idx < (HD / 2) * HD) {
        int p = idx / HD, j = idx - p * HD;
        g_Wf_p[idx] = pk2(Wf[(2 * p) * HD + j], Wf[(2 * p + 1) * HD + j]);
    }
    if (idx < HD) {
        g_bin_pad[idx]  = bin[idx];
        g_bmix_pad[idx] = bmix[idx];
        g_bzr[idx]       = bz[idx];
        g_bzr[256 + idx] = br[idx];
        g_bh_pad[idx]   = bh[idx];
    }
}

// ---------------- tf32 tensor-core GEMM, BM=64 x BN=256, fused epilogues ----------------
// MODE 0: h = relu(X @ Win + bin)                    K=128
// MODE 1: m = relu(agg @ Wcomb + bmix)               K=224
// MODE 2: [z|r] = sig([m|h] @ Wzr + bzr); rh = r*h   K=448, N=512 (grid.y=2)
// MODE 3: h = (1-z)h + z*tanh([m|rh] @ Whh + bh)     K=448
template<int MODE, int KC_TOT, int KC1, int SA, int SB>
__global__ void __launch_bounds__(256) k_gemm(const float* __restrict__ Aext) {
    __shared__ __align__(16) float sA[2][BM][BK + 4];
    __shared__ __align__(16) float sB[2][BK][BN + 8];
    const int t = threadIdx.x;
    const int bm = blockIdx.x * BM;
    const int n0 = blockIdx.y * BN;
    const int lane = t & 31, w = t >> 5;
    const int wr = (w >> 2) * 32;     // 2 row-warps
    const int wc = (w & 3) * 64;      // 4 col-warps

    const float* Bw;
    const float* bias;
    if (MODE == 0) { Bw = g_Win_pad; bias = g_bin_pad; }
    else if (MODE == 1) { Bw = g_Wcomb; bias = g_bmix_pad; }
    else if (MODE == 2) { Bw = g_Wzr; bias = g_bzr; }
    else { Bw = g_Whh; bias = g_bh_pad; }

    const int ar = t >> 2, akc = (t & 3) * 4;   // A stage: 1 float4/thread
    const int brk = t >> 4, bcc = (t & 15) * 16; // B stage: 4 float4/thread (cp.async)

    float4 ra;
    auto ldgA = [&](int c) {
        const float* Ap; int koff;
        if (c < KC1) {
            Ap = (MODE == 0) ? Aext : ((MODE == 1) ? g_agg : g_m);
            koff = c * BK;
        } else {
            Ap = (MODE == 2) ? g_h : g_rh;
            koff = (c - KC1) * BK;
        }
        int g0 = bm + ar;
        ra = (g0 < NN) ? *(const float4*)(Ap + (size_t)g0 * SA + koff + akc)
                       : make_float4(0.f, 0.f, 0.f, 0.f);
    };
    auto stsA = [&](int buf) {
        *(float4*)&sA[buf][ar][akc] =
            make_float4(tf32f(ra.x), tf32f(ra.y), tf32f(ra.z), tf32f(ra.w));
    };
    auto cpB = [&](int c, int buf) {
        const float* src = Bw + (size_t)(c * BK + brk) * SB + n0 + bcc;
        unsigned dst = (unsigned)__cvta_generic_to_shared(&sB[buf][brk][bcc]);
#pragma unroll
        for (int i = 0; i < 4; i++)
            asm volatile("cp.async.ca.shared.global [%0],[%1],16;"
                         :: "r"(dst + i * 16), "l"(src + i * 4));
        asm volatile("cp.async.commit_group;");
    };

    float acc[2][8][4];
#pragma unroll
    for (int rt = 0; rt < 2; rt++)
#pragma unroll
        for (int ct = 0; ct < 8; ct++)
#pragma unroll
            for (int e = 0; e < 4; e++) acc[rt][ct][e] = 0.0f;

    auto compute = [&](int buf) {
#pragma unroll
        for (int ks = 0; ks < BK; ks += 8) {
            unsigned a[2][4], b[8][2];
            int kk = ks + (lane & 3);
            int q = lane >> 2;
#pragma unroll
            for (int rt = 0; rt < 2; rt++) {
                int r0 = wr + rt * 16 + q;
                a[rt][0] = __float_as_uint(sA[buf][r0][kk]);
                a[rt][1] = __float_as_uint(sA[buf][r0 + 8][kk]);
                a[rt][2] = __float_as_uint(sA[buf][r0][kk + 4]);
                a[rt][3] = __float_as_uint(sA[buf][r0 + 8][kk + 4]);
            }
#pragma unroll
            for (int ct = 0; ct < 8; ct++) {
                int cn = wc + ct * 8 + q;
                b[ct][0] = __float_as_uint(sB[buf][kk][cn]);
                b[ct][1] = __float_as_uint(sB[buf][kk + 4][cn]);
            }
#pragma unroll
            for (int rt = 0; rt < 2; rt++)
#pragma unroll
                for (int ct = 0; ct < 8; ct++)
                    asm volatile(
                        "mma.sync.aligned.m16n8k8.row.col.f32.tf32.tf32.f32 "
                        "{%0,%1,%2,%3},{%4,%5,%6,%7},{%8,%9},{%0,%1,%2,%3};"
                        : "+f"(acc[rt][ct][0]), "+f"(acc[rt][ct][1]),
                          "+f"(acc[rt][ct][2]), "+f"(acc[rt][ct][3])
                        : "r"(a[rt][0]), "r"(a[rt][1]), "r"(a[rt][2]), "r"(a[rt][3]),
                          "r"(b[ct][0]), "r"(b[ct][1]));
        }
    };

    ldgA(0); cpB(0, 0); stsA(0);
    asm volatile("cp.async.wait_group 0;");
    __syncthreads();
#pragma unroll 1
    for (int c = 0; c < KC_TOT; c++) {
        int buf = c & 1;
        if (c + 1 < KC_TOT) { ldgA(c + 1); cpB(c + 1, buf ^ 1); }
        compute(buf);
        if (c + 1 < KC_TOT) {
            asm volatile("cp.async.wait_group 0;");
            stsA(buf ^ 1);
            __syncthreads();
        }
    }

    // ---- epilogue ----
#pragma unroll
    for (int rt = 0; rt < 2; rt++) {
        int r_lo = wr + rt * 16 + (lane >> 2);
#pragma unroll
        for (int half = 0; half < 2; half++) {
            int gr = bm + r_lo + half * 8;
            if (gr >= NN) continue;
#pragma unroll
            for (int ct = 0; ct < 8; ct++) {
#pragma unroll
                for (int e = 0; e < 2; e++) {
                    int cn = wc + ct * 8 + (lane & 3) * 2 + e;
                    int gn = n0 + cn;
                    float v = acc[rt][ct][half * 2 + e] + bias[gn];
                    if (MODE == 0) {
                        if (gn < HP) g_h[(size_t)gr * HP + gn] = fmaxf(v, 0.0f);
                    } else if (MODE == 1) {
                        if (gn < HP) g_m[(size_t)gr * HP + gn] = fmaxf(v, 0.0f);
                    } else if (MODE == 2) {
                        if (gn < 256) {
                            if (gn < HP) g_z[(size_t)gr * HP + gn] = sigf(v);
                        } else {
                            int cc = gn - 256;
                            if (cc < HP) {
                                float hv = g_h[(size_t)gr * HP + cc];
                                g_rh[(size_t)gr * HP + cc] = sigf(v) * hv;
                            }
                        }
                    } else {
                        if (gn < HP) {
                            float hprev = g_h[(size_t)gr * HP + gn];
                            float zz = g_z[(size_t)gr * HP + gn];
                            g_h[(size_t)gr * HP + gn] =
                                (1.0f - zz) * hprev + zz * tanhf(v);
                        }
                    }
                }
            }
        }
    }
}

// ---------------- edge_gate = sigmoid(EF @ W_edge + b_edge) -> fp16 ----------------
__global__ void k_eg(const float* __restrict__ EF, const float* __restrict__ W,
                     const float* __restrict__ b) {
    __shared__ __align__(16) float sX[RE][FED];
    int base = blockIdx.x * RE;
    const float4* src = (const float4*)(EF + (size_t)base * FED);
    for (int i = threadIdx.x; i < RE * FED / 4; i += blockDim.x)
        ((float4*)sX)[i] = src[i];
    __syncthreads();
    int j = threadIdx.x;
    if (j >= HD) return;
    float acc[RE];
#pragma unroll
    for (int i = 0; i < RE; i++) acc[i] = b[j];
#pragma unroll
    for (int k = 0; k < FED; k++) {
        float w = W[k * HD + j];
#pragma unroll
        for (int i = 0; i < RE; i++) acc[i] += sX[i][k] * w;
    }
#pragma unroll
    for (int i = 0; i < RE; i++)
        g_eg[(size_t)(base + i) * HD + j] = __float2half_rn(sigf(acc[i]));
}

// ---------------- zero agg (full padded width) ----------------
__global__ void k_zero_agg() {
    int i = blockIdx.x * blockDim.x + threadIdx.x;
    if (i < NN * HP / 4) ((float4*)g_agg)[i] = make_float4(0.f, 0.f, 0.f, 0.f);
}

// ---------------- scatter: agg[dst] += eg[e] * h[src]  (fp16 gate, v4 red) ----------------
__global__ void k_scatter(const int* __restrict__ ei) {
    int idx = blockIdx.x * blockDim.x + threadIdx.x;
    if (idx >= NE * (HD / 4)) return;
    int e = idx / (HD / 4);
    int c = (idx - e * (HD / 4)) * 4;
    int s = ei[e];
    int d = ei[NE + e];
    uint2 raw = *(const uint2*)&g_eg[(size_t)e * HD + c];
    float2 e01 = __half22float2(*(__half2*)&raw.x);
    float2 e23 = __half22float2(*(__half2*)&raw.y);
    float4 hv = *(const float4*)&g_h[(size_t)s * HP + c];
    float vx = e01.x * hv.x, vy = e01.y * hv.y;
    float vz = e23.x * hv.z, vw = e23.y * hv.w;
    float* p = &g_agg[(size_t)d * HP + c];
    asm volatile("red.global.add.v4.f32 [%0],{%1,%2,%3,%4};"
                 :: "l"(p), "f"(vx), "f"(vy), "f"(vz), "f"(vw) : "memory");
}

// ---------------- init readout scratch ----------------
__global__ void k_init_small() {
    int t = blockIdx.x * blockDim.x + threadIdx.x;
    for (int i = t; i < NG * HD; i += gridDim.x * blockDim.x) g_gfeat[i] = 0.0f;
    if (t < NG) { g_denom[t] = 0.0f; g_smax[t] = enc_f(-INFINITY); }
}

// ---------------- score + segment max ----------------
__global__ void k_score(const float* __restrict__ Ws, const float* __restrict__ bs,
                        const int* __restrict__ bv) {
    int n = blockIdx.x * 8 + (threadIdx.x >> 5);
    if (n >= NN) return;
    int lane = threadIdx.x & 31;
    float acc = 0.0f;
    for (int k = lane; k < HD; k += 32) acc += g_h[(size_t)n * HP + k] * Ws[k];
#pragma unroll
    for (int o = 16; o; o >>= 1) acc += __shfl_xor_sync(0xffffffffu, acc, o);
    if (lane == 0) {
        float s = acc + bs[0];
        g_score[n] = s;
        atomicMax(&g_smax[bv[n]], enc_f(s));
    }
}

// ---------------- exp + segment sum ----------------
__global__ void k_exp(const int* __restrict__ bv) {
    int n0 = (blockIdx.x * blockDim.x + threadIdx.x) * 16;
    if (n0 >= NN) return;
    int end = n0 + 16; if (end > NN) end = NN;
    int cb = bv[n0];
    float mx = dec_f(g_smax[cb]);
    float run = 0.0f;
    for (int n = n0; n < end; n++) {
        int b = bv[n];
        if (b != cb) {
            atomicAdd(&g_denom[cb], run);
            run = 0.0f; cb = b; mx = dec_f(g_smax[b]);
        }
        float ex = __expf(g_score[n] - mx);
        g_ex[n] = ex;
        run += ex;
    }
    atomicAdd(&g_denom[cb], run);
}

// ---------------- feat = h@W_feat + b_feat; g[b] += alpha*feat ----------------
__global__ void k_feat(const float* __restrict__ bf, const int* __restrict__ bv) {
    __shared__ __align__(16) float sHt[RT][HD];
    __shared__ float sAl[RT];
    __shared__ int   sB[RT];
    int base = blockIdx.x * RT;
    for (int i = threadIdx.x; i < RT * (HD / 4); i += blockDim.x) {
        int row = i / (HD / 4), c4 = i % (HD / 4);
        *(float4*)&sHt[row][c4 * 4] =
            *(const float4*)&g_h[(size_t)(base + row) * HP + c4 * 4];
    }
    if (threadIdx.x < RT) {
        int n = base + threadIdx.x;
        int b = bv[n];
        sB[threadIdx.x] = b;
        sAl[threadIdx.x] = g_ex[n] / g_denom[b];
    }
    __syncthreads();
    int j = threadIdx.x;
    if (j >= HD) return;
    u64 acc[RT];
#pragma unroll
    for (int i = 0; i < RT; i++) acc[i] = pk2(bf[j], 0.0f);
    for (int k = 0; k < HD; k += 4) {
        u64 w01 = g_Wf_p[(k / 2) * HD + j];
        u64 w23 = g_Wf_p[(k / 2 + 1) * HD + j];
#pragma unroll
        for (int i = 0; i < RT; i++) {
            ulonglong2 h = *(const ulonglong2*)&sHt[i][k];
            fma2(acc[i], h.x, w01);
            fma2(acc[i], h.y, w23);
        }
    }
    float run = 0.0f;
    int cb = sB[0];
#pragma unroll
    for (int i = 0; i < RT; i++) {
        if (sB[i] != cb) {
            atomicAdd(&g_gfeat[cb * HD + j], run);
            run = 0.0f; cb = sB[i];
        }
        run += sAl[i] * red2(acc[i]);
    }
    atomicAdd(&g_gfeat[cb * HD + j], run);
}

// ---------------- readout MLP ----------------
__global__ void k_readout(const float* __restrict__ Wr1, const float* __restrict__ br1,
                          const float* __restrict__ Wout, const float* __restrict__ bout,
                          float* __restrict__ out) {
    __shared__ float sG[HD];
    __shared__ float sRed[256];
    int g = blockIdx.x;
    for (int k = threadIdx.x; k < HD; k += blockDim.x) sG[k] = g_gfeat[g * HD + k];
    __syncthreads();
    float p = 0.0f;
    int j = threadIdx.x;
    if (j < HD) {
        float acc = br1[j];
        for (int k = 0; k < HD; k++) acc += sG[k] * Wr1[k * HD + j];
        p = fmaxf(acc, 0.0f) * Wout[j];
    }
    sRed[threadIdx.x] = p;
    __syncthreads();
    for (int s = 128; s; s >>= 1) {
        if (threadIdx.x < s) sRed[threadIdx.x] += sRed[threadIdx.x + s];
        __syncthreads();
    }
    if (threadIdx.x == 0) out[g] = sRed[0] + bout[0];
}

// ---------------- launch ----------------
extern "C" void kernel_launch(void* const* d_in, const int* in_sizes, int n_in,
                              void* d_out, int out_size) {
    const float* node_features = (const float*)d_in[0];
    const float* edge_features = (const float*)d_in[1];
    const int*   edge_index    = (const int*)d_in[2];
    const int*   batch_vector  = (const int*)d_in[3];
    const float* W_in   = (const float*)d_in[4];
    const float* b_in   = (const float*)d_in[5];
    const float* W_edge = (const float*)d_in[6];
    const float* b_edge = (const float*)d_in[7];
    const float* W_tower= (const float*)d_in[8];
    const float* W_mix  = (const float*)d_in[9];
    const float* b_mix  = (const float*)d_in[10];
    const float* Wz = (const float*)d_in[11];
    const float* Uz = (const float*)d_in[12];
    const float* bz = (const float*)d_in[13];
    const float* Wr = (const float*)d_in[14];
    const float* Ur = (const float*)d_in[15];
    const float* br = (const float*)d_in[16];
    const float* Wh = (const float*)d_in[17];
    const float* Uh = (const float*)d_in[18];
    const float* bh = (const float*)d_in[19];
    const float* W_score = (const float*)d_in[20];
    const float* b_score = (const float*)d_in[21];
    const float* W_feat  = (const float*)d_in[22];
    const float* b_feat  = (const float*)d_in[23];
    const float* W_r1    = (const float*)d_in[24];
    const float* b_r1    = (const float*)d_in[25];
    const float* W_out   = (const float*)d_in[26];
    const float* b_out   = (const float*)d_in[27];
    float* out = (float*)d_out;

    k_pack_all<<<(HD * HD + 255) / 256, 256>>>(
        W_in, b_in, W_tower, W_mix, b_mix, Wz, Uz, bz, Wr, Ur, br, Wh, Uh, bh, W_feat);

    const int GX = (NN + BM - 1) / BM;   // 1563
    k_gemm<0, FND / BK, FND / BK, FND, 256><<<dim3(GX, 1), 256>>>(node_features);
    k_eg<<<NE / RE, 224>>>(edge_features, W_edge, b_edge);

    for (int s = 0; s < NSTEPS; s++) {
        k_zero_agg<<<(NN * HP / 4 + 255) / 256, 256>>>();
        k_scatter<<<(NE * (HD / 4) + 255) / 256, 256>>>(edge_index);
        k_gemm<1, HP / BK, HP / BK, HP, 256><<<dim3(GX, 1), 256>>>(nullptr);
        k_gemm<2, 2 * HP / BK, HP / BK, HP, 512><<<dim3(GX, 2), 256>>>(nullptr);
        k_gemm<3, 2 * HP / BK, HP / BK, HP, 256><<<dim3(GX, 1), 256>>>(nullptr);
    }

    k_init_small<<<50, 256>>>();
    k_score<<<(NN + 7) / 8, 256>>>(W_score, b_score, batch_vector);
    k_exp<<<(NN / 16 + 255) / 256, 256>>>(batch_vector);
    k_feat<<<NN / RT, 224>>>(b_feat, batch_vector);
    k_readout<<<NG, 256>>>(W_r1, b_r1, W_out, b_out, out);
}